// round 1
// baseline (speedup 1.0000x reference)
#include <cuda_runtime.h>
#include <stdint.h>

#define NN 4096      // nodes
#define NE 65536     // edges
#define FD 128       // node feature dim
#define HD 256       // hidden dim

// ---------------- scratch (device globals; no allocations allowed) ----------------
__device__ __align__(16) float    g_T[NN * 768];       // [node | P | Q] per row (stride 768)
__device__ __align__(16) float    g_C[NN * 768];       // [node | mean1 | mean2] per row
__device__ __align__(16) float    g_sub_h[NN * HD];
__device__ __align__(16) float    g_nbh_h[NN * HD];
__device__ __align__(16) float    g_Wcat[FD * 768];    // [Wn | We_a | We_b]
__device__ __align__(16) float    g_bcat[768];
__device__ unsigned g_B[NN * 128];                      // out-neighbor bitmasks
__device__ int g_rowptr[NN + 1];
__device__ int g_colidx[NE];
__device__ int g_cnt[NN];
__device__ int g_cur[NN];

// ---------------- zero scratch ----------------
__global__ void zero_all_k() {
    int i = blockIdx.x * blockDim.x + threadIdx.x;
    if (i < NN) { g_cnt[i] = 0; g_cur[i] = 0; }
    // bitmask: NN*128 = 524288 words
    for (int w = i; w < NN * 128; w += gridDim.x * blockDim.x) g_B[w] = 0u;
}

// ---------------- pack fused weight [Wn | We_a | We_b] and bias [bn | be | 0] ----------------
__global__ void pack_w_k(const float* __restrict__ Wn, const float* __restrict__ bn,
                         const float* __restrict__ We, const float* __restrict__ be) {
    int idx = blockIdx.x * blockDim.x + threadIdx.x;
    if (idx < FD * 768) {
        int k = idx / 768, c = idx % 768;
        float v;
        if (c < 256)       v = Wn[k * 256 + c];
        else if (c < 512)  v = We[k * 256 + (c - 256)];
        else               v = We[(128 + k) * 256 + (c - 512)];
        g_Wcat[idx] = v;
    }
    if (idx < 768) {
        g_bcat[idx] = (idx < 256) ? bn[idx] : ((idx < 512) ? be[idx - 256] : 0.f);
    }
}

// ---------------- generic 64x64-tile fp32 GEMM: C = A(MxK,lda) * B(KxN,ldb) + bias, optional relu ----
__global__ __launch_bounds__(256)
void sgemm64_k(const float* __restrict__ A, int lda,
               const float* __restrict__ B, int ldb,
               const float* __restrict__ bias,
               float* __restrict__ C, int ldc,
               int K, int relu) {
    __shared__ __align__(16) float As[16][64];
    __shared__ __align__(16) float Bs[16][64];
    int tid = threadIdx.x;
    int tx = tid & 15;     // 0..15 -> 4 output cols each
    int ty = tid >> 4;     // 0..15 -> 4 output rows each
    int m0 = blockIdx.y * 64;
    int n0 = blockIdx.x * 64;

    float acc[4][4] = {};
    int la_m = tid >> 2;          // 0..63
    int la_k = (tid & 3) << 2;    // 0,4,8,12
    int lb_k = tid >> 4;          // 0..15
    int lb_n = (tid & 15) << 2;   // 0..60

    const float* Aptr = A + (size_t)(m0 + la_m) * lda + la_k;
    const float* Bptr = B + (size_t)lb_k * ldb + n0 + lb_n;

    for (int kb = 0; kb < K; kb += 16) {
        float4 av = *(const float4*)(Aptr + kb);
        As[la_k + 0][la_m] = av.x;
        As[la_k + 1][la_m] = av.y;
        As[la_k + 2][la_m] = av.z;
        As[la_k + 3][la_m] = av.w;
        float4 bv = *(const float4*)(Bptr + (size_t)kb * ldb);
        *(float4*)&Bs[lb_k][lb_n] = bv;
        __syncthreads();
#pragma unroll
        for (int kk = 0; kk < 16; kk++) {
            float4 a = *(float4*)&As[kk][ty * 4];
            float4 b = *(float4*)&Bs[kk][tx * 4];
            acc[0][0] += a.x * b.x; acc[0][1] += a.x * b.y; acc[0][2] += a.x * b.z; acc[0][3] += a.x * b.w;
            acc[1][0] += a.y * b.x; acc[1][1] += a.y * b.y; acc[1][2] += a.y * b.z; acc[1][3] += a.y * b.w;
            acc[2][0] += a.z * b.x; acc[2][1] += a.z * b.y; acc[2][2] += a.z * b.z; acc[2][3] += a.z * b.w;
            acc[3][0] += a.w * b.x; acc[3][1] += a.w * b.y; acc[3][2] += a.w * b.z; acc[3][3] += a.w * b.w;
        }
        __syncthreads();
    }

    float4 bb = bias ? *(const float4*)&bias[n0 + tx * 4] : make_float4(0.f, 0.f, 0.f, 0.f);
#pragma unroll
    for (int r = 0; r < 4; r++) {
        int m = m0 + ty * 4 + r;
        float4 v;
        v.x = acc[r][0] + bb.x; v.y = acc[r][1] + bb.y;
        v.z = acc[r][2] + bb.z; v.w = acc[r][3] + bb.w;
        if (relu) {
            v.x = fmaxf(v.x, 0.f); v.y = fmaxf(v.y, 0.f);
            v.z = fmaxf(v.z, 0.f); v.w = fmaxf(v.w, 0.f);
        }
        *(float4*)&C[(size_t)m * ldc + n0 + tx * 4] = v;
    }
}

// ---------------- CSR build ----------------
__global__ void hist_k(const int* __restrict__ ei) {
    int e = blockIdx.x * blockDim.x + threadIdx.x;
    if (e < NE) atomicAdd(&g_cnt[ei[e]], 1);
}

__global__ void scan_k() {
    __shared__ int s[1024];
    int t = threadIdx.x;
    int b = t * 4;
    int c0 = g_cnt[b], c1 = g_cnt[b + 1], c2 = g_cnt[b + 2], c3 = g_cnt[b + 3];
    int sum = c0 + c1 + c2 + c3;
    s[t] = sum;
    __syncthreads();
    for (int off = 1; off < 1024; off <<= 1) {
        int v = (t >= off) ? s[t - off] : 0;
        __syncthreads();
        s[t] += v;
        __syncthreads();
    }
    int excl = s[t] - sum;
    g_rowptr[b]     = excl;
    g_rowptr[b + 1] = excl + c0;
    g_rowptr[b + 2] = excl + c0 + c1;
    g_rowptr[b + 3] = excl + c0 + c1 + c2;
    if (t == 1023) g_rowptr[NN] = excl + sum;
}

__global__ void fill_k(const int* __restrict__ ei) {
    int e = blockIdx.x * blockDim.x + threadIdx.x;
    if (e < NE) {
        int r = ei[e];
        int pos = g_rowptr[r] + atomicAdd(&g_cur[r], 1);
        g_colidx[pos] = ei[NE + e];
    }
}

// ---------------- out-neighbor bitmasks ----------------
__global__ void buildB_k(const int* __restrict__ ei) {
    int e = blockIdx.x * blockDim.x + threadIdx.x;
    if (e < NE) {
        int r = ei[e], c = ei[NE + e];
        atomicOr(&g_B[(unsigned)r * 128u + (c >> 5)], 1u << (c & 31));
    }
}

// ---------------- mean1 + node copy (block = node, thread = feature) ----------------
__global__ __launch_bounds__(256)
void mean1_k(float* __restrict__ out_node) {
    int i = blockIdx.x, h = threadIdx.x;
    int s = g_rowptr[i], e = g_rowptr[i + 1];
    float a0 = 0.f, a1 = 0.f, a2 = 0.f, a3 = 0.f;
    int p = s;
    for (; p + 4 <= e; p += 4) {
        int j0 = g_colidx[p], j1 = g_colidx[p + 1], j2 = g_colidx[p + 2], j3 = g_colidx[p + 3];
        a0 += g_T[(size_t)j0 * 768 + h];
        a1 += g_T[(size_t)j1 * 768 + h];
        a2 += g_T[(size_t)j2 * 768 + h];
        a3 += g_T[(size_t)j3 * 768 + h];
    }
    for (; p < e; p++) a0 += g_T[(size_t)g_colidx[p] * 768 + h];
    float acc = (a0 + a1) + (a2 + a3);
    int deg = e - s;
    float m = deg > 0 ? acc / (float)deg : 0.f;
    float nd = g_T[(size_t)i * 768 + h];
    g_C[(size_t)i * 768 + h] = nd;
    g_C[(size_t)i * 768 + 256 + h] = m;
    out_node[(size_t)i * 256 + h] = nd;
}

// ---------------- mean2: dedup'd 2-hop neighborhood mean (block = node) ----------------
__global__ __launch_bounds__(256)
void mean2_k() {
    __shared__ unsigned rm[128];
    __shared__ int sc[128];
    __shared__ unsigned short list[NN];
    int i = blockIdx.x, t = threadIdx.x;
    int s = g_rowptr[i], e = g_rowptr[i + 1];

    // rowmask = OR over out-neighbors k of outmask[k]; clear self bit
    if (t < 128) {
        unsigned m = 0u;
        for (int p = s; p < e; p++) {
            int k = g_colidx[p];
            m |= g_B[(unsigned)k * 128u + t];
        }
        if (t == (i >> 5)) m &= ~(1u << (i & 31));
        rm[t] = m;
        sc[t] = __popc(m);
    }
    __syncthreads();
    // prefix-sum of popcounts (deterministic extraction order)
    for (int off = 1; off < 128; off <<= 1) {
        int v = 0;
        if (t < 128 && t >= off) v = sc[t - off];
        __syncthreads();
        if (t < 128) sc[t] += v;
        __syncthreads();
    }
    if (t < 128) {
        unsigned m = rm[t];
        int o = sc[t] - __popc(m);
        int base = t << 5;
        while (m) {
            int b = __ffs(m) - 1;
            m &= m - 1;
            list[o++] = (unsigned short)(base + b);
        }
    }
    __syncthreads();
    int cnt = sc[127];

    float a0 = 0.f, a1 = 0.f, a2 = 0.f, a3 = 0.f;
    int p = 0;
    for (; p + 4 <= cnt; p += 4) {
        int j0 = list[p], j1 = list[p + 1], j2 = list[p + 2], j3 = list[p + 3];
        a0 += g_T[(size_t)j0 * 768 + t];
        a1 += g_T[(size_t)j1 * 768 + t];
        a2 += g_T[(size_t)j2 * 768 + t];
        a3 += g_T[(size_t)j3 * 768 + t];
    }
    for (; p < cnt; p++) a0 += g_T[(size_t)list[p] * 768 + t];
    float acc = (a0 + a1) + (a2 + a3);
    float m2 = cnt > 0 ? acc / (float)cnt : 0.f;
    g_C[(size_t)i * 768 + 512 + t] = m2;
}

// ---------------- edge assembly: edge[e] = P[row[e]] + Q[col[e]] (be already in P) ----------------
__global__ __launch_bounds__(256)
void edge_k(const int* __restrict__ ei, float* __restrict__ out_edge) {
    int gid = blockIdx.x * 256 + threadIdx.x;
    int e = gid >> 6;            // 64 threads per edge
    int c = (gid & 63) << 2;     // float offset within row
    int r = ei[e], cl = ei[NE + e];
    float4 p = *(const float4*)&g_T[(size_t)r * 768 + 256 + c];
    float4 q = *(const float4*)&g_T[(size_t)cl * 768 + 512 + c];
    float4 o;
    o.x = p.x + q.x; o.y = p.y + q.y; o.z = p.z + q.z; o.w = p.w + q.w;
    *(float4*)&out_edge[(size_t)e * 256 + c] = o;
}

// ---------------- launch ----------------
extern "C" void kernel_launch(void* const* d_in, const int* in_sizes, int n_in,
                              void* d_out, int out_size) {
    const float* x   = (const float*)d_in[0];
    const int*   ei  = (const int*)  d_in[1];
    const float* Wn  = (const float*)d_in[2];
    const float* bn  = (const float*)d_in[3];
    const float* We  = (const float*)d_in[4];
    const float* be  = (const float*)d_in[5];
    const float* Ws1 = (const float*)d_in[6];
    const float* bs1 = (const float*)d_in[7];
    const float* Ws2 = (const float*)d_in[8];
    const float* bs2 = (const float*)d_in[9];
    const float* Wh1 = (const float*)d_in[10];
    const float* bh1 = (const float*)d_in[11];
    const float* Wh2 = (const float*)d_in[12];
    const float* bh2 = (const float*)d_in[13];

    float* out      = (float*)d_out;
    float* out_node = out;
    float* out_edge = out_node + (size_t)NN * HD;
    float* out_sub  = out_edge + (size_t)NE * HD;
    float* out_nbh  = out_sub  + (size_t)NN * HD;

    zero_all_k<<<64, 256>>>();
    pack_w_k<<<(FD * 768 + 255) / 256, 256>>>(Wn, bn, We, be);

    // T = x @ [Wn|We_a|We_b] + [bn|be|0]   (M=4096, K=128, N=768)
    {
        float *wc, *bc, *T;
        cudaGetSymbolAddress((void**)&wc, g_Wcat);
        cudaGetSymbolAddress((void**)&bc, g_bcat);
        cudaGetSymbolAddress((void**)&T,  g_T);
        sgemm64_k<<<dim3(12, 64), 256>>>(x, FD, wc, 768, bc, T, 768, FD, 0);
    }

    hist_k<<<NE / 256, 256>>>(ei);
    scan_k<<<1, 1024>>>();
    fill_k<<<NE / 256, 256>>>(ei);
    buildB_k<<<NE / 256, 256>>>(ei);

    mean1_k<<<NN, 256>>>(out_node);
    mean2_k<<<NN, 256>>>();
    edge_k<<<(NE * 64) / 256, 256>>>(ei, out_edge);

    {
        float *C, *sh, *nh;
        cudaGetSymbolAddress((void**)&C,  g_C);
        cudaGetSymbolAddress((void**)&sh, g_sub_h);
        cudaGetSymbolAddress((void**)&nh, g_nbh_h);
        // sub = relu([node|mean1] @ Ws1 + bs1) @ Ws2 + bs2
        sgemm64_k<<<dim3(4, 64), 256>>>(C, 768, Ws1, 256, bs1, sh, 256, 512, 1);
        sgemm64_k<<<dim3(4, 64), 256>>>(sh, 256, Ws2, 256, bs2, out_sub, 256, 256, 0);
        // nbh = relu([node|mean1|mean2] @ Wh1 + bh1) @ Wh2 + bh2
        sgemm64_k<<<dim3(4, 64), 256>>>(C, 768, Wh1, 256, bh1, nh, 256, 768, 1);
        sgemm64_k<<<dim3(4, 64), 256>>>(nh, 256, Wh2, 256, bh2, out_nbh, 256, 256, 0);
    }
}

// round 4
// speedup vs baseline: 1.0444x; 1.0444x over previous
#include <cuda_runtime.h>
#include <cuda_bf16.h>
#include <cuda_pipeline.h>
#include <mma.h>
#include <stdint.h>

using namespace nvcuda;

#define NN 4096      // nodes
#define NE 65536     // edges
#define FD 128       // node feature dim
#define HD 256       // hidden dim

// ======================= scratch (device globals) =======================
__device__ __align__(16) float g_T[NN * 768];       // [node | P | Q] stride 768
__device__ __align__(16) float g_C[NN * 768];       // [node | mean1 | mean2]
__device__ __align__(16) float g_sub_h[NN * HD];
__device__ __align__(16) float g_nbh_h[NN * HD];
__device__ __align__(16) float g_bcat[768];

__device__ __align__(16) __nv_bfloat16 g_xh[NN * FD],  g_xl[NN * FD];
__device__ __align__(16) __nv_bfloat16 g_Ch[NN * 768], g_Cl[NN * 768];
__device__ __align__(16) __nv_bfloat16 g_shh[NN * HD], g_shl[NN * HD];
__device__ __align__(16) __nv_bfloat16 g_nhh[NN * HD], g_nhl[NN * HD];
__device__ __align__(16) __nv_bfloat16 g_btc_h[768 * FD],  g_btc_l[768 * FD];   // [N=768][K=128]
__device__ __align__(16) __nv_bfloat16 g_bs1_h[HD * 512],  g_bs1_l[HD * 512];
__device__ __align__(16) __nv_bfloat16 g_bs2_h[HD * HD],   g_bs2_l[HD * HD];
__device__ __align__(16) __nv_bfloat16 g_bh1_h[HD * 768],  g_bh1_l[HD * 768];
__device__ __align__(16) __nv_bfloat16 g_bh2_h[HD * HD],   g_bh2_l[HD * HD];

// bias-as-K-extension blocks
__device__ __align__(16) __nv_bfloat16 g_extA[128 * 32];       // ones in cols 0,1
__device__ __align__(16) __nv_bfloat16 g_extB1[768 * 32];      // bcat
__device__ __align__(16) __nv_bfloat16 g_extB2[256 * 32];      // bs1
__device__ __align__(16) __nv_bfloat16 g_extB3[256 * 32];      // bs2
__device__ __align__(16) __nv_bfloat16 g_extB4[256 * 32];      // bh1
__device__ __align__(16) __nv_bfloat16 g_extB5[256 * 32];      // bh2

__device__ unsigned g_B[NN * 128];
__device__ int g_rowptr[NN + 1];
__device__ int g_colidx[NE];
__device__ int g_cnt[NN];
__device__ int g_cur[NN];

// ======================= small prep kernels =======================
__global__ void zero_all_k() {
    int i = blockIdx.x * blockDim.x + threadIdx.x;
    if (i < NN) { g_cnt[i] = 0; g_cur[i] = 0; }
    for (int w = i; w < NN * 128; w += gridDim.x * blockDim.x) g_B[w] = 0u;
    if (i < 128 * 32) g_extA[i] = __float2bfloat16(((i & 31) < 2) ? 1.f : 0.f);
}

__device__ __forceinline__ void split1(float a, __nv_bfloat16& h, __nv_bfloat16& l) {
    h = __float2bfloat16(a);
    l = __float2bfloat16(a - __bfloat162float(h));
}

__global__ void cvt_split_k(const float* __restrict__ A,
                            __nv_bfloat16* __restrict__ hi,
                            __nv_bfloat16* __restrict__ lo, int n) {
    int i = blockIdx.x * blockDim.x + threadIdx.x;
    if (i < n) { __nv_bfloat16 h, l; split1(A[i], h, l); hi[i] = h; lo[i] = l; }
}

// transpose + split: W[K][N] -> Bt[N][K]
__global__ void wtr_split_k(const float* __restrict__ W,
                            __nv_bfloat16* __restrict__ bh,
                            __nv_bfloat16* __restrict__ bl, int K, int N) {
    int i = blockIdx.x * blockDim.x + threadIdx.x;
    if (i < K * N) {
        int k = i / N, n = i % N;
        __nv_bfloat16 h, l; split1(W[i], h, l);
        bh[n * K + k] = h; bl[n * K + k] = l;
    }
}

// fused [Wn | We_top | We_bot] transposed to [768][128] + bias cat
__global__ void wcat_k(const float* __restrict__ Wn, const float* __restrict__ bn,
                       const float* __restrict__ We, const float* __restrict__ be) {
    int i = blockIdx.x * blockDim.x + threadIdx.x;
    if (i < 768 * FD) {
        int n = i / FD, k = i % FD;
        float v;
        if (n < 256)      v = Wn[k * 256 + n];
        else if (n < 512) v = We[k * 256 + (n - 256)];
        else              v = We[(128 + k) * 256 + (n - 512)];
        __nv_bfloat16 h, l; split1(v, h, l);
        g_btc_h[n * FD + k] = h; g_btc_l[n * FD + k] = l;
    }
    if (i < 768)
        g_bcat[i] = (i < 256) ? bn[i] : ((i < 512) ? be[i - 256] : 0.f);
}

// bias -> ext-K block: eB[n][0]=bias_h, eB[n][1]=bias_l, rest 0
__global__ void extB_k(const float* __restrict__ bias, __nv_bfloat16* __restrict__ eB, int n) {
    int i = blockIdx.x * blockDim.x + threadIdx.x;
    if (i < n * 32) {
        int r = i >> 5, k = i & 31;
        __nv_bfloat16 h, l; split1(bias[r], h, l);
        eB[i] = (k == 0) ? h : ((k == 1) ? l : __float2bfloat16(0.f));
    }
}

// ======================= wmma bf16x3 GEMM =======================
// C[M, Ntot] = A[M,K] @ Bt[Ntot,K]^T + bias (via ext-K), optional relu
// CTA tile 64(M) x 128(N), 256 threads (8 warps of 32x32), K chunks of 32,
// cp.async double buffer. K-extension: [Ah|Al|Ah] x [Bh|Bh|Bl] + bias chunk.
#define AK 48   // smem K stride (bf16 elems); 96B rows, 32B-aligned

__global__ __launch_bounds__(256)
void gemm_wmma(const __nv_bfloat16* __restrict__ Ah, const __nv_bfloat16* __restrict__ Al, int lda,
               const __nv_bfloat16* __restrict__ Bh, const __nv_bfloat16* __restrict__ Bl, int ldb,
               const __nv_bfloat16* __restrict__ extB,
               float* __restrict__ C, int ldc, int K, int relu) {
    __shared__ __align__(128) __nv_bfloat16 As[2][64][AK];
    __shared__ __align__(128) __nv_bfloat16 Bs[2][128][AK];

    int tid = threadIdx.x;
    int m0 = blockIdx.y * 64;
    int n0 = blockIdx.x * 128;
    int nmain = (3 * K) >> 5;
    int nch = nmain + 1;   // + bias chunk

    int wid = tid >> 5;
    int wm = wid & 1;      // 2 M-warps
    int wn = wid >> 1;     // 4 N-warps

    wmma::fragment<wmma::accumulator, 16, 16, 16, float> acc[2][2];
#pragma unroll
    for (int fm = 0; fm < 2; fm++)
#pragma unroll
        for (int fn = 0; fn < 2; fn++)
            wmma::fill_fragment(acc[fm][fn], 0.f);

    auto issue = [&](int c, int s) {
        const __nv_bfloat16 *Asrc, *Bsrc;
        int alda, blda;
        if (c < nmain) {
            int kb = c << 5;
            int seg = kb / K;
            int off = kb - seg * K;
            Asrc = ((seg == 1) ? Al : Ah) + (size_t)m0 * lda + off; alda = lda;
            Bsrc = ((seg == 2) ? Bl : Bh) + (size_t)n0 * ldb + off; blda = ldb;
        } else {
            Asrc = g_extA;                alda = 32;
            Bsrc = extB + (size_t)n0 * 32; blda = 32;
        }
        int r = tid >> 2, kq = (tid & 3) * 8;
        __pipeline_memcpy_async(&As[s][r][kq],      Asrc + (size_t)r * alda + kq, 16);
        __pipeline_memcpy_async(&Bs[s][r][kq],      Bsrc + (size_t)r * blda + kq, 16);
        __pipeline_memcpy_async(&Bs[s][r + 64][kq], Bsrc + (size_t)(r + 64) * blda + kq, 16);
    };

    issue(0, 0);
    __pipeline_commit();

    for (int c = 0; c < nch; c++) {
        if (c + 1 < nch) {
            issue(c + 1, (c + 1) & 1);
            __pipeline_commit();
            __pipeline_wait_prior(1);
        } else {
            __pipeline_wait_prior(0);
        }
        __syncthreads();
        int s = c & 1;
#pragma unroll
        for (int ks = 0; ks < 32; ks += 16) {
            wmma::fragment<wmma::matrix_a, 16, 16, 16, __nv_bfloat16, wmma::row_major> a[2];
            wmma::fragment<wmma::matrix_b, 16, 16, 16, __nv_bfloat16, wmma::col_major> b[2];
#pragma unroll
            for (int fm = 0; fm < 2; fm++)
                wmma::load_matrix_sync(a[fm], &As[s][wm * 32 + fm * 16][ks], AK);
#pragma unroll
            for (int fn = 0; fn < 2; fn++)
                wmma::load_matrix_sync(b[fn], &Bs[s][wn * 32 + fn * 16][ks], AK);
#pragma unroll
            for (int fm = 0; fm < 2; fm++)
#pragma unroll
                for (int fn = 0; fn < 2; fn++)
                    wmma::mma_sync(acc[fm][fn], a[fm], b[fn], acc[fm][fn]);
        }
        __syncthreads();
    }

    // epilogue: relu (elementwise, mapping-agnostic), direct global store
#pragma unroll
    for (int fm = 0; fm < 2; fm++)
#pragma unroll
        for (int fn = 0; fn < 2; fn++) {
            if (relu) {
#pragma unroll
                for (int i = 0; i < acc[fm][fn].num_elements; i++)
                    acc[fm][fn].x[i] = fmaxf(acc[fm][fn].x[i], 0.f);
            }
            wmma::store_matrix_sync(
                &C[(size_t)(m0 + wm * 32 + fm * 16) * ldc + n0 + wn * 32 + fn * 16],
                acc[fm][fn], ldc, wmma::mem_row_major);
        }
}

// ======================= CSR build =======================
__global__ void hist_k(const int* __restrict__ ei) {
    int e = blockIdx.x * blockDim.x + threadIdx.x;
    if (e < NE) atomicAdd(&g_cnt[ei[e]], 1);
}

__global__ void scan_k() {
    __shared__ int s[1024];
    int t = threadIdx.x;
    int b = t * 4;
    int c0 = g_cnt[b], c1 = g_cnt[b + 1], c2 = g_cnt[b + 2], c3 = g_cnt[b + 3];
    int sum = c0 + c1 + c2 + c3;
    s[t] = sum;
    __syncthreads();
    for (int off = 1; off < 1024; off <<= 1) {
        int v = (t >= off) ? s[t - off] : 0;
        __syncthreads();
        s[t] += v;
        __syncthreads();
    }
    int excl = s[t] - sum;
    g_rowptr[b]     = excl;
    g_rowptr[b + 1] = excl + c0;
    g_rowptr[b + 2] = excl + c0 + c1;
    g_rowptr[b + 3] = excl + c0 + c1 + c2;
    if (t == 1023) g_rowptr[NN] = excl + sum;
}

__global__ void fill_k(const int* __restrict__ ei) {
    int e = blockIdx.x * blockDim.x + threadIdx.x;
    if (e < NE) {
        int r = ei[e];
        int pos = g_rowptr[r] + atomicAdd(&g_cur[r], 1);
        g_colidx[pos] = ei[NE + e];
    }
}

__global__ void buildB_k(const int* __restrict__ ei) {
    int e = blockIdx.x * blockDim.x + threadIdx.x;
    if (e < NE) {
        int r = ei[e], c = ei[NE + e];
        atomicOr(&g_B[(unsigned)r * 128u + (c >> 5)], 1u << (c & 31));
    }
}

// ======================= mean1 + node copy =======================
__global__ __launch_bounds__(256)
void mean1_k(float* __restrict__ out_node) {
    int i = blockIdx.x, h = threadIdx.x;
    int s = g_rowptr[i], e = g_rowptr[i + 1];
    float a0 = 0.f, a1 = 0.f, a2 = 0.f, a3 = 0.f;
    int p = s;
    for (; p + 4 <= e; p += 4) {
        int j0 = g_colidx[p], j1 = g_colidx[p + 1], j2 = g_colidx[p + 2], j3 = g_colidx[p + 3];
        a0 += g_T[(size_t)j0 * 768 + h];
        a1 += g_T[(size_t)j1 * 768 + h];
        a2 += g_T[(size_t)j2 * 768 + h];
        a3 += g_T[(size_t)j3 * 768 + h];
    }
    for (; p < e; p++) a0 += g_T[(size_t)g_colidx[p] * 768 + h];
    float acc = (a0 + a1) + (a2 + a3);
    int deg = e - s;
    float m = deg > 0 ? acc / (float)deg : 0.f;
    float nd = g_T[(size_t)i * 768 + h];
    g_C[(size_t)i * 768 + h] = nd;
    g_C[(size_t)i * 768 + 256 + h] = m;
    out_node[(size_t)i * 256 + h] = nd;
}

// ======================= mean2: dedup'd 2-hop mean =======================
__global__ __launch_bounds__(256)
void mean2_k() {
    __shared__ unsigned rm[128];
    __shared__ int sc[128];
    __shared__ unsigned short list[NN];
    int i = blockIdx.x, t = threadIdx.x;
    int s = g_rowptr[i], e = g_rowptr[i + 1];

    if (t < 128) {
        unsigned m = 0u;
        for (int p = s; p < e; p++) {
            int k = g_colidx[p];
            m |= g_B[(unsigned)k * 128u + t];
        }
        if (t == (i >> 5)) m &= ~(1u << (i & 31));
        rm[t] = m;
        sc[t] = __popc(m);
    }
    __syncthreads();
    for (int off = 1; off < 128; off <<= 1) {
        int v = 0;
        if (t < 128 && t >= off) v = sc[t - off];
        __syncthreads();
        if (t < 128) sc[t] += v;
        __syncthreads();
    }
    if (t < 128) {
        unsigned m = rm[t];
        int o = sc[t] - __popc(m);
        int base = t << 5;
        while (m) {
            int b = __ffs(m) - 1;
            m &= m - 1;
            list[o++] = (unsigned short)(base + b);
        }
    }
    __syncthreads();
    int cnt = sc[127];

    float a0 = 0.f, a1 = 0.f, a2 = 0.f, a3 = 0.f;
    int p = 0;
    for (; p + 4 <= cnt; p += 4) {
        int j0 = list[p], j1 = list[p + 1], j2 = list[p + 2], j3 = list[p + 3];
        a0 += g_T[(size_t)j0 * 768 + t];
        a1 += g_T[(size_t)j1 * 768 + t];
        a2 += g_T[(size_t)j2 * 768 + t];
        a3 += g_T[(size_t)j3 * 768 + t];
    }
    for (; p < cnt; p++) a0 += g_T[(size_t)list[p] * 768 + t];
    float acc = (a0 + a1) + (a2 + a3);
    float m2 = cnt > 0 ? acc / (float)cnt : 0.f;
    g_C[(size_t)i * 768 + 512 + t] = m2;
}

// ======================= edge assembly =======================
__global__ __launch_bounds__(256)
void edge_k(const int* __restrict__ ei, float* __restrict__ out_edge) {
    int gid = blockIdx.x * 256 + threadIdx.x;
    int e = gid >> 6;
    int c = (gid & 63) << 2;
    int r = ei[e], cl = ei[NE + e];
    float4 p = *(const float4*)&g_T[(size_t)r * 768 + 256 + c];
    float4 q = *(const float4*)&g_T[(size_t)cl * 768 + 512 + c];
    float4 o;
    o.x = p.x + q.x; o.y = p.y + q.y; o.z = p.z + q.z; o.w = p.w + q.w;
    *(float4*)&out_edge[(size_t)e * 256 + c] = o;
}

// ======================= launch =======================
extern "C" void kernel_launch(void* const* d_in, const int* in_sizes, int n_in,
                              void* d_out, int out_size) {
    const float* x   = (const float*)d_in[0];
    const int*   ei  = (const int*)  d_in[1];
    const float* Wn  = (const float*)d_in[2];
    const float* bn  = (const float*)d_in[3];
    const float* We  = (const float*)d_in[4];
    const float* be  = (const float*)d_in[5];
    const float* Ws1 = (const float*)d_in[6];
    const float* bs1 = (const float*)d_in[7];
    const float* Ws2 = (const float*)d_in[8];
    const float* bs2 = (const float*)d_in[9];
    const float* Wh1 = (const float*)d_in[10];
    const float* bh1 = (const float*)d_in[11];
    const float* Wh2 = (const float*)d_in[12];
    const float* bh2 = (const float*)d_in[13];

    float* out      = (float*)d_out;
    float* out_node = out;
    float* out_edge = out_node + (size_t)NN * HD;
    float* out_sub  = out_edge + (size_t)NE * HD;
    float* out_nbh  = out_sub  + (size_t)NN * HD;

    float *T, *C, *sh, *nh, *bc;
    cudaGetSymbolAddress((void**)&T,  g_T);
    cudaGetSymbolAddress((void**)&C,  g_C);
    cudaGetSymbolAddress((void**)&sh, g_sub_h);
    cudaGetSymbolAddress((void**)&nh, g_nbh_h);
    cudaGetSymbolAddress((void**)&bc, g_bcat);
    __nv_bfloat16 *xh, *xl, *Chh, *Cll, *shh, *shl, *nhh, *nhl;
    __nv_bfloat16 *btc_h, *btc_l, *bs1h, *bs1l, *bs2h, *bs2l, *bh1h, *bh1l, *bh2h, *bh2l;
    __nv_bfloat16 *eB1, *eB2, *eB3, *eB4, *eB5;
    cudaGetSymbolAddress((void**)&xh, g_xh);   cudaGetSymbolAddress((void**)&xl, g_xl);
    cudaGetSymbolAddress((void**)&Chh, g_Ch);  cudaGetSymbolAddress((void**)&Cll, g_Cl);
    cudaGetSymbolAddress((void**)&shh, g_shh); cudaGetSymbolAddress((void**)&shl, g_shl);
    cudaGetSymbolAddress((void**)&nhh, g_nhh); cudaGetSymbolAddress((void**)&nhl, g_nhl);
    cudaGetSymbolAddress((void**)&btc_h, g_btc_h); cudaGetSymbolAddress((void**)&btc_l, g_btc_l);
    cudaGetSymbolAddress((void**)&bs1h, g_bs1_h);  cudaGetSymbolAddress((void**)&bs1l, g_bs1_l);
    cudaGetSymbolAddress((void**)&bs2h, g_bs2_h);  cudaGetSymbolAddress((void**)&bs2l, g_bs2_l);
    cudaGetSymbolAddress((void**)&bh1h, g_bh1_h);  cudaGetSymbolAddress((void**)&bh1l, g_bh1_l);
    cudaGetSymbolAddress((void**)&bh2h, g_bh2_h);  cudaGetSymbolAddress((void**)&bh2l, g_bh2_l);
    cudaGetSymbolAddress((void**)&eB1, g_extB1);
    cudaGetSymbolAddress((void**)&eB2, g_extB2);
    cudaGetSymbolAddress((void**)&eB3, g_extB3);
    cudaGetSymbolAddress((void**)&eB4, g_extB4);
    cudaGetSymbolAddress((void**)&eB5, g_extB5);

    zero_all_k<<<64, 256>>>();
    cvt_split_k<<<(NN * FD + 255) / 256, 256>>>(x, xh, xl, NN * FD);
    wcat_k<<<(768 * FD + 255) / 256, 256>>>(Wn, bn, We, be);
    wtr_split_k<<<(512 * 256 + 255) / 256, 256>>>(Ws1, bs1h, bs1l, 512, 256);
    wtr_split_k<<<(256 * 256 + 255) / 256, 256>>>(Ws2, bs2h, bs2l, 256, 256);
    wtr_split_k<<<(768 * 256 + 255) / 256, 256>>>(Wh1, bh1h, bh1l, 768, 256);
    wtr_split_k<<<(256 * 256 + 255) / 256, 256>>>(Wh2, bh2h, bh2l, 256, 256);
    extB_k<<<(768 * 32 + 255) / 256, 256>>>(bc,  eB1, 768);
    extB_k<<<(256 * 32 + 255) / 256, 256>>>(bs1, eB2, 256);
    extB_k<<<(256 * 32 + 255) / 256, 256>>>(bs2, eB3, 256);
    extB_k<<<(256 * 32 + 255) / 256, 256>>>(bh1, eB4, 256);
    extB_k<<<(256 * 32 + 255) / 256, 256>>>(bh2, eB5, 256);

    // G1: T = x @ [Wn|We_a|We_b] + bcat   M=4096 K=128 N=768
    gemm_wmma<<<dim3(6, 64), 256>>>(xh, xl, FD, btc_h, btc_l, FD, eB1, T, 768, FD, 0);

    hist_k<<<NE / 256, 256>>>(ei);
    scan_k<<<1, 1024>>>();
    fill_k<<<NE / 256, 256>>>(ei);
    buildB_k<<<NE / 256, 256>>>(ei);

    mean1_k<<<NN, 256>>>(out_node);
    mean2_k<<<NN, 256>>>();
    edge_k<<<(NE * 64) / 256, 256>>>(ei, out_edge);

    cvt_split_k<<<(NN * 768 + 255) / 256, 256>>>(C, Chh, Cll, NN * 768);

    // G2: sub_h = relu(C[:, :512] @ Ws1 + bs1)   K=512 N=256
    gemm_wmma<<<dim3(2, 64), 256>>>(Chh, Cll, 768, bs1h, bs1l, 512, eB2, sh, 256, 512, 1);
    cvt_split_k<<<(NN * HD + 255) / 256, 256>>>(sh, shh, shl, NN * HD);
    // G3: out_sub = sub_h @ Ws2 + bs2   K=256 N=256
    gemm_wmma<<<dim3(2, 64), 256>>>(shh, shl, 256, bs2h, bs2l, 256, eB3, out_sub, 256, 256, 0);

    // G4: nbh_h = relu(C @ Wh1 + bh1)   K=768 N=256
    gemm_wmma<<<dim3(2, 64), 256>>>(Chh, Cll, 768, bh1h, bh1l, 768, eB4, nh, 256, 768, 1);
    cvt_split_k<<<(NN * HD + 255) / 256, 256>>>(nh, nhh, nhl, NN * HD);
    // G5: out_nbh = nbh_h @ Wh2 + bh2   K=256 N=256
    gemm_wmma<<<dim3(2, 64), 256>>>(nhh, nhl, 256, bh2h, bh2l, 256, eB5, out_nbh, 256, 256, 0);
}

// round 6
// speedup vs baseline: 1.2706x; 1.2165x over previous
#include <cuda_runtime.h>
#include <cuda_bf16.h>
#include <cuda_pipeline.h>
#include <mma.h>
#include <stdint.h>

using namespace nvcuda;

#define NN 4096      // nodes
#define NE 65536     // edges
#define FD 128       // node feature dim
#define HD 256       // hidden dim

// ======================= scratch (device globals) =======================
__device__ __align__(16) float g_T[NN * 768];                 // [node | P | Q] stride 768

__device__ __align__(16) __nv_bfloat16 g_Tbh[NN * HD];        // node tokens bf16 (gather source)
__device__ __align__(16) __nv_bfloat16 g_xh[NN * FD],  g_xl[NN * FD];
__device__ __align__(16) __nv_bfloat16 g_Ch[NN * 768], g_Cl[NN * 768];   // [node|mean1|mean2] h/l
__device__ __align__(16) __nv_bfloat16 g_shh[NN * HD], g_shl[NN * HD];
__device__ __align__(16) __nv_bfloat16 g_nhh[NN * HD], g_nhl[NN * HD];
__device__ __align__(16) __nv_bfloat16 g_btc_h[768 * FD],  g_btc_l[768 * FD];   // [N=768][K=128]
__device__ __align__(16) __nv_bfloat16 g_bs1_h[HD * 512],  g_bs1_l[HD * 512];   // [256][512]
__device__ __align__(16) __nv_bfloat16 g_bs2_h[HD * HD],   g_bs2_l[HD * HD];
__device__ __align__(16) __nv_bfloat16 g_bh1_h[HD * 768],  g_bh1_l[HD * 768];
__device__ __align__(16) __nv_bfloat16 g_bh2_h[HD * HD],   g_bh2_l[HD * HD];

// bias-as-K-extension blocks
__device__ __align__(16) __nv_bfloat16 g_extA[128 * 32];      // ones in cols 0,1
__device__ __align__(16) __nv_bfloat16 g_extB1[768 * 32];     // [bn|be|0]
__device__ __align__(16) __nv_bfloat16 g_extB2[256 * 32];     // bs1
__device__ __align__(16) __nv_bfloat16 g_extB3[256 * 32];     // bs2
__device__ __align__(16) __nv_bfloat16 g_extB4[256 * 32];     // bh1
__device__ __align__(16) __nv_bfloat16 g_extB5[256 * 32];     // bh2

__device__ unsigned g_B[NN * 128];
__device__ int g_rowptr[NN + 1];
__device__ int g_colidx[NE];
__device__ int g_cnt[NN];
__device__ int g_cur[NN];

__device__ __forceinline__ void split1(float a, __nv_bfloat16& h, __nv_bfloat16& l) {
    h = __float2bfloat16(a);
    l = __float2bfloat16(a - __bfloat162float(h));
}

// ======================= fused prep (all weight/bias transforms + zeroing) =======================
// flat-index segments; total items = 1,671,168
__global__ __launch_bounds__(256)
void prep_k(const float* __restrict__ x,
            const float* __restrict__ Wn,  const float* __restrict__ bn,
            const float* __restrict__ We,  const float* __restrict__ be,
            const float* __restrict__ Ws1, const float* __restrict__ bs1,
            const float* __restrict__ Ws2, const float* __restrict__ bs2,
            const float* __restrict__ Wh1, const float* __restrict__ bh1,
            const float* __restrict__ Wh2, const float* __restrict__ bh2) {
    int idx = blockIdx.x * 256 + threadIdx.x;
    // s0: cnt/cur zero + extA (8192)
    if (idx < 8192) {
        if (idx < 4096) { g_cnt[idx] = 0; g_cur[idx] = 0; }
        else {
            int i = idx - 4096;
            g_extA[i] = __float2bfloat16(((i & 31) < 2) ? 1.f : 0.f);
        }
        return;
    }
    idx -= 8192;
    if (idx < 524288) { g_B[idx] = 0u; return; }          // zero bitmasks
    idx -= 524288;
    if (idx < 524288) {                                    // x -> h/l
        __nv_bfloat16 h, l; split1(x[idx], h, l);
        g_xh[idx] = h; g_xl[idx] = l;
        return;
    }
    idx -= 524288;
    if (idx < 98304) {                                     // [Wn|We_a|We_b]^T -> btc
        int n = idx / FD, k = idx % FD;
        float v;
        if (n < 256)      v = Wn[k * 256 + n];
        else if (n < 512) v = We[k * 256 + (n - 256)];
        else              v = We[(128 + k) * 256 + (n - 512)];
        __nv_bfloat16 h, l; split1(v, h, l);
        g_btc_h[n * FD + k] = h; g_btc_l[n * FD + k] = l;
        return;
    }
    idx -= 98304;
    if (idx < 24576) {                                     // extB1 (bcat)
        int r = idx >> 5, k = idx & 31;
        float b = (r < 256) ? bn[r] : ((r < 512) ? be[r - 256] : 0.f);
        __nv_bfloat16 h, l; split1(b, h, l);
        g_extB1[idx] = (k == 0) ? h : ((k == 1) ? l : __float2bfloat16(0.f));
        return;
    }
    idx -= 24576;
    if (idx < 131072) {                                    // Ws1 [512][256] -> [256][512]
        int kk = idx >> 8, n = idx & 255;
        __nv_bfloat16 h, l; split1(Ws1[idx], h, l);
        g_bs1_h[n * 512 + kk] = h; g_bs1_l[n * 512 + kk] = l;
        return;
    }
    idx -= 131072;
    if (idx < 65536) {                                     // Ws2 [256][256]
        int kk = idx >> 8, n = idx & 255;
        __nv_bfloat16 h, l; split1(Ws2[idx], h, l);
        g_bs2_h[n * 256 + kk] = h; g_bs2_l[n * 256 + kk] = l;
        return;
    }
    idx -= 65536;
    if (idx < 196608) {                                    // Wh1 [768][256] -> [256][768]
        int kk = idx >> 8, n = idx & 255;
        __nv_bfloat16 h, l; split1(Wh1[idx], h, l);
        g_bh1_h[n * 768 + kk] = h; g_bh1_l[n * 768 + kk] = l;
        return;
    }
    idx -= 196608;
    if (idx < 65536) {                                     // Wh2 [256][256]
        int kk = idx >> 8, n = idx & 255;
        __nv_bfloat16 h, l; split1(Wh2[idx], h, l);
        g_bh2_h[n * 256 + kk] = h; g_bh2_l[n * 256 + kk] = l;
        return;
    }
    idx -= 65536;
    {
        const float* bias;
        __nv_bfloat16* dst;
        if (idx < 8192)       { bias = bs1; dst = g_extB2; }
        else if (idx < 16384) { bias = bs2; dst = g_extB3; idx -= 8192; }
        else if (idx < 24576) { bias = bh1; dst = g_extB4; idx -= 16384; }
        else                  { bias = bh2; dst = g_extB5; idx -= 24576; }
        int r = idx >> 5, k = idx & 31;
        __nv_bfloat16 h, l; split1(bias[r], h, l);
        dst[idx] = (k == 0) ? h : ((k == 1) ? l : __float2bfloat16(0.f));
    }
}

// ======================= wmma bf16x3 GEMM =======================
// C[M, Ntot] = A[M,K] @ Bt[Ntot,K]^T + bias (via ext-K), optional relu
// CTA tile 64(M) x 128(N), 8 warps (32x32 each), K chunks of 32, cp.async 2-stage.
// Output: if Cf != null -> fp32 store; else -> bf16 h/l split store (Oh/Ol).
#define AK 48   // smem K stride (bf16 elems); 96B rows

__global__ __launch_bounds__(256)
void gemm_wmma(const __nv_bfloat16* __restrict__ Ah, const __nv_bfloat16* __restrict__ Al, int lda,
               const __nv_bfloat16* __restrict__ Bh, const __nv_bfloat16* __restrict__ Bl, int ldb,
               const __nv_bfloat16* __restrict__ extB,
               float* __restrict__ Cf, int ldc,
               __nv_bfloat16* __restrict__ Oh, __nv_bfloat16* __restrict__ Ol, int ldo,
               int K, int relu) {
    __shared__ __align__(128) char smbuf[36864];
    auto As = reinterpret_cast<__nv_bfloat16(*)[64][AK]>(smbuf);           // [2][64][48]  12288B
    auto Bs = reinterpret_cast<__nv_bfloat16(*)[128][AK]>(smbuf + 12288);  // [2][128][48] 24576B

    int tid = threadIdx.x;
    int m0 = blockIdx.y * 64;
    int n0 = blockIdx.x * 128;
    int nmain = (3 * K) >> 5;
    int nch = nmain + 1;   // + bias chunk

    int wid = tid >> 5;
    int wm = wid & 1;      // 2 M-warps
    int wn = wid >> 1;     // 4 N-warps

    wmma::fragment<wmma::accumulator, 16, 16, 16, float> acc[2][2];
#pragma unroll
    for (int fm = 0; fm < 2; fm++)
#pragma unroll
        for (int fn = 0; fn < 2; fn++)
            wmma::fill_fragment(acc[fm][fn], 0.f);

    auto issue = [&](int c, int s) {
        const __nv_bfloat16 *Asrc, *Bsrc;
        int alda, blda;
        if (c < nmain) {
            int kb = c << 5;
            int seg = kb / K;
            int off = kb - seg * K;
            Asrc = ((seg == 1) ? Al : Ah) + (size_t)m0 * lda + off; alda = lda;
            Bsrc = ((seg == 2) ? Bl : Bh) + (size_t)n0 * ldb + off; blda = ldb;
        } else {
            Asrc = g_extA;                 alda = 32;
            Bsrc = extB + (size_t)n0 * 32; blda = 32;
        }
        int r = tid >> 2, kq = (tid & 3) * 8;
        __pipeline_memcpy_async(&As[s][r][kq],      Asrc + (size_t)r * alda + kq, 16);
        __pipeline_memcpy_async(&Bs[s][r][kq],      Bsrc + (size_t)r * blda + kq, 16);
        __pipeline_memcpy_async(&Bs[s][r + 64][kq], Bsrc + (size_t)(r + 64) * blda + kq, 16);
    };

    issue(0, 0);
    __pipeline_commit();

    for (int c = 0; c < nch; c++) {
        if (c + 1 < nch) {
            issue(c + 1, (c + 1) & 1);
            __pipeline_commit();
            __pipeline_wait_prior(1);
        } else {
            __pipeline_wait_prior(0);
        }
        __syncthreads();
        int s = c & 1;
#pragma unroll
        for (int ks = 0; ks < 32; ks += 16) {
            wmma::fragment<wmma::matrix_a, 16, 16, 16, __nv_bfloat16, wmma::row_major> a[2];
            wmma::fragment<wmma::matrix_b, 16, 16, 16, __nv_bfloat16, wmma::col_major> b[2];
#pragma unroll
            for (int fm = 0; fm < 2; fm++)
                wmma::load_matrix_sync(a[fm], &As[s][wm * 32 + fm * 16][ks], AK);
#pragma unroll
            for (int fn = 0; fn < 2; fn++)
                wmma::load_matrix_sync(b[fn], &Bs[s][wn * 32 + fn * 16][ks], AK);
#pragma unroll
            for (int fm = 0; fm < 2; fm++)
#pragma unroll
                for (int fn = 0; fn < 2; fn++)
                    wmma::mma_sync(acc[fm][fn], a[fm], b[fn], acc[fm][fn]);
        }
        __syncthreads();
    }

    // relu in fragments (mapping-agnostic)
    if (relu) {
#pragma unroll
        for (int fm = 0; fm < 2; fm++)
#pragma unroll
            for (int fn = 0; fn < 2; fn++)
#pragma unroll
                for (int i = 0; i < acc[fm][fn].num_elements; i++)
                    acc[fm][fn].x[i] = fmaxf(acc[fm][fn].x[i], 0.f);
    }

    if (Cf) {
#pragma unroll
        for (int fm = 0; fm < 2; fm++)
#pragma unroll
            for (int fn = 0; fn < 2; fn++)
                wmma::store_matrix_sync(
                    &Cf[(size_t)(m0 + wm * 32 + fm * 16) * ldc + n0 + wn * 32 + fn * 16],
                    acc[fm][fn], ldc, wmma::mem_row_major);
    } else {
        // bf16 h/l split epilogue via smem (reuses smbuf; prior __syncthreads done)
        float* epi = (float*)smbuf;   // [64][132]  33792B
#pragma unroll
        for (int fm = 0; fm < 2; fm++)
#pragma unroll
            for (int fn = 0; fn < 2; fn++)
                wmma::store_matrix_sync(
                    &epi[(wm * 32 + fm * 16) * 132 + wn * 32 + fn * 16],
                    acc[fm][fn], 132, wmma::mem_row_major);
        __syncthreads();
        for (int idx = tid; idx < 64 * 128; idx += 256) {
            int row = idx >> 7, col = idx & 127;
            float v = epi[row * 132 + col];
            __nv_bfloat16 h, l; split1(v, h, l);
            size_t o = (size_t)(m0 + row) * ldo + n0 + col;
            Oh[o] = h; Ol[o] = l;
        }
    }
}

// ======================= CSR build =======================
__global__ void hist_k(const int* __restrict__ ei) {
    int e = blockIdx.x * blockDim.x + threadIdx.x;
    if (e < NE) atomicAdd(&g_cnt[ei[e]], 1);
}

__global__ void scan_k() {
    __shared__ int s[1024];
    int t = threadIdx.x;
    int b = t * 4;
    int c0 = g_cnt[b], c1 = g_cnt[b + 1], c2 = g_cnt[b + 2], c3 = g_cnt[b + 3];
    int sum = c0 + c1 + c2 + c3;
    s[t] = sum;
    __syncthreads();
    for (int off = 1; off < 1024; off <<= 1) {
        int v = (t >= off) ? s[t - off] : 0;
        __syncthreads();
        s[t] += v;
        __syncthreads();
    }
    int excl = s[t] - sum;
    g_rowptr[b]     = excl;
    g_rowptr[b + 1] = excl + c0;
    g_rowptr[b + 2] = excl + c0 + c1;
    g_rowptr[b + 3] = excl + c0 + c1 + c2;
    if (t == 1023) g_rowptr[NN] = excl + sum;
}

__global__ void fill_k(const int* __restrict__ ei) {
    int e = blockIdx.x * blockDim.x + threadIdx.x;
    if (e < NE) {
        int r = ei[e];
        int pos = g_rowptr[r] + atomicAdd(&g_cur[r], 1);
        g_colidx[pos] = ei[NE + e];
    }
}

// ======================= misc: bitmask build + node->bf16 copy =======================
__global__ __launch_bounds__(256)
void misc_k(const int* __restrict__ ei) {
    int idx = blockIdx.x * 256 + threadIdx.x;
    if (idx < NN * HD) {
        int row = idx >> 8, col = idx & 255;
        g_Tbh[idx] = __float2bfloat16(g_T[(size_t)row * 768 + col]);
    } else {
        int e = idx - NN * HD;
        if (e < NE) {
            int r = ei[e], c = ei[NE + e];
            atomicOr(&g_B[(unsigned)r * 128u + (c >> 5)], 1u << (c & 31));
        }
    }
}

// ======================= mean1 + node copy + bf16 h/l writes =======================
__global__ __launch_bounds__(256)
void mean1_k(float* __restrict__ out_node) {
    int i = blockIdx.x, h = threadIdx.x;
    int s = g_rowptr[i], e = g_rowptr[i + 1];
    float a0 = 0.f, a1 = 0.f, a2 = 0.f, a3 = 0.f;
    int p = s;
    for (; p + 4 <= e; p += 4) {
        int j0 = g_colidx[p], j1 = g_colidx[p + 1], j2 = g_colidx[p + 2], j3 = g_colidx[p + 3];
        a0 += g_T[(size_t)j0 * 768 + h];
        a1 += g_T[(size_t)j1 * 768 + h];
        a2 += g_T[(size_t)j2 * 768 + h];
        a3 += g_T[(size_t)j3 * 768 + h];
    }
    for (; p < e; p++) a0 += g_T[(size_t)g_colidx[p] * 768 + h];
    float acc = (a0 + a1) + (a2 + a3);
    int deg = e - s;
    float m = deg > 0 ? acc / (float)deg : 0.f;
    float nd = g_T[(size_t)i * 768 + h];
    out_node[(size_t)i * 256 + h] = nd;
    __nv_bfloat16 hh, ll;
    split1(nd, hh, ll);
    g_Ch[(size_t)i * 768 + h] = hh; g_Cl[(size_t)i * 768 + h] = ll;
    split1(m, hh, ll);
    g_Ch[(size_t)i * 768 + 256 + h] = hh; g_Cl[(size_t)i * 768 + 256 + h] = ll;
}

// ======================= mean2: dedup'd 2-hop mean (bf16 gather) =======================
__global__ __launch_bounds__(256)
void mean2_k() {
    __shared__ unsigned rm[128];
    __shared__ int sc[128];
    __shared__ float2 part[128];
    __shared__ unsigned short list[NN];
    int i = blockIdx.x, t = threadIdx.x;
    int s = g_rowptr[i], e = g_rowptr[i + 1];

    if (t < 128) {
        unsigned m = 0u;
        for (int p = s; p < e; p++) {
            int k = g_colidx[p];
            m |= g_B[(unsigned)k * 128u + t];
        }
        if (t == (i >> 5)) m &= ~(1u << (i & 31));
        rm[t] = m;
        sc[t] = __popc(m);
    }
    __syncthreads();
    for (int off = 1; off < 128; off <<= 1) {
        int v = 0;
        if (t < 128 && t >= off) v = sc[t - off];
        __syncthreads();
        if (t < 128) sc[t] += v;
        __syncthreads();
    }
    if (t < 128) {
        unsigned m = rm[t];
        int o = sc[t] - __popc(m);
        int base = t << 5;
        while (m) {
            int b = __ffs(m) - 1;
            m &= m - 1;
            list[o++] = (unsigned short)(base + b);
        }
    }
    __syncthreads();
    int cnt = sc[127];

    // gather from bf16 node copy: thread (p,h) -> column pair p, rows of parity h
    const unsigned* Tb = (const unsigned*)g_Tbh;   // [NN][128] words
    int p = t & 127, hh = t >> 7;
    float ax = 0.f, ay = 0.f, bx = 0.f, by = 0.f;
    int r = hh;
    for (; r + 2 < cnt; r += 4) {
        unsigned w0 = Tb[(unsigned)list[r] * 128u + p];
        unsigned w1 = Tb[(unsigned)list[r + 2] * 128u + p];
        __nv_bfloat162 v0 = *(__nv_bfloat162*)&w0;
        __nv_bfloat162 v1 = *(__nv_bfloat162*)&w1;
        ax += __bfloat162float(v0.x); ay += __bfloat162float(v0.y);
        bx += __bfloat162float(v1.x); by += __bfloat162float(v1.y);
    }
    for (; r < cnt; r += 2) {
        unsigned w = Tb[(unsigned)list[r] * 128u + p];
        __nv_bfloat162 v = *(__nv_bfloat162*)&w;
        ax += __bfloat162float(v.x); ay += __bfloat162float(v.y);
    }
    float sx = ax + bx, sy = ay + by;
    if (hh) part[p] = make_float2(sx, sy);
    __syncthreads();
    if (!hh) {
        sx += part[p].x; sy += part[p].y;
        float m0v = cnt > 0 ? sx / (float)cnt : 0.f;
        float m1v = cnt > 0 ? sy / (float)cnt : 0.f;
        __nv_bfloat16 h0, l0, h1, l1;
        split1(m0v, h0, l0);
        split1(m1v, h1, l1);
        __nv_bfloat162 ph; ph.x = h0; ph.y = h1;
        __nv_bfloat162 pl; pl.x = l0; pl.y = l1;
        *(__nv_bfloat162*)&g_Ch[(size_t)i * 768 + 512 + 2 * p] = ph;
        *(__nv_bfloat162*)&g_Cl[(size_t)i * 768 + 512 + 2 * p] = pl;
    }
}

// ======================= edge assembly =======================
__global__ __launch_bounds__(256)
void edge_k(const int* __restrict__ ei, float* __restrict__ out_edge) {
    int gid = blockIdx.x * 256 + threadIdx.x;
    int e = gid >> 6;
    int c = (gid & 63) << 2;
    int r = ei[e], cl = ei[NE + e];
    float4 p = *(const float4*)&g_T[(size_t)r * 768 + 256 + c];
    float4 q = *(const float4*)&g_T[(size_t)cl * 768 + 512 + c];
    float4 o;
    o.x = p.x + q.x; o.y = p.y + q.y; o.z = p.z + q.z; o.w = p.w + q.w;
    *(float4*)&out_edge[(size_t)e * 256 + c] = o;
}

// ======================= launch =======================
extern "C" void kernel_launch(void* const* d_in, const int* in_sizes, int n_in,
                              void* d_out, int out_size) {
    const float* x   = (const float*)d_in[0];
    const int*   ei  = (const int*)  d_in[1];
    const float* Wn  = (const float*)d_in[2];
    const float* bn  = (const float*)d_in[3];
    const float* We  = (const float*)d_in[4];
    const float* be  = (const float*)d_in[5];
    const float* Ws1 = (const float*)d_in[6];
    const float* bs1 = (const float*)d_in[7];
    const float* Ws2 = (const float*)d_in[8];
    const float* bs2 = (const float*)d_in[9];
    const float* Wh1 = (const float*)d_in[10];
    const float* bh1 = (const float*)d_in[11];
    const float* Wh2 = (const float*)d_in[12];
    const float* bh2 = (const float*)d_in[13];

    float* out      = (float*)d_out;
    float* out_node = out;
    float* out_edge = out_node + (size_t)NN * HD;
    float* out_sub  = out_edge + (size_t)NE * HD;
    float* out_nbh  = out_sub  + (size_t)NN * HD;

    float* T;
    cudaGetSymbolAddress((void**)&T, g_T);
    __nv_bfloat16 *xh, *xl, *Chh, *Cll, *shh, *shl, *nhh, *nhl;
    __nv_bfloat16 *btc_h, *btc_l, *bs1h, *bs1l, *bs2h, *bs2l, *bh1h, *bh1l, *bh2h, *bh2l;
    __nv_bfloat16 *eB1, *eB2, *eB3, *eB4, *eB5;
    cudaGetSymbolAddress((void**)&xh, g_xh);   cudaGetSymbolAddress((void**)&xl, g_xl);
    cudaGetSymbolAddress((void**)&Chh, g_Ch);  cudaGetSymbolAddress((void**)&Cll, g_Cl);
    cudaGetSymbolAddress((void**)&shh, g_shh); cudaGetSymbolAddress((void**)&shl, g_shl);
    cudaGetSymbolAddress((void**)&nhh, g_nhh); cudaGetSymbolAddress((void**)&nhl, g_nhl);
    cudaGetSymbolAddress((void**)&btc_h, g_btc_h); cudaGetSymbolAddress((void**)&btc_l, g_btc_l);
    cudaGetSymbolAddress((void**)&bs1h, g_bs1_h);  cudaGetSymbolAddress((void**)&bs1l, g_bs1_l);
    cudaGetSymbolAddress((void**)&bs2h, g_bs2_h);  cudaGetSymbolAddress((void**)&bs2l, g_bs2_l);
    cudaGetSymbolAddress((void**)&bh1h, g_bh1_h);  cudaGetSymbolAddress((void**)&bh1l, g_bh1_l);
    cudaGetSymbolAddress((void**)&bh2h, g_bh2_h);  cudaGetSymbolAddress((void**)&bh2l, g_bh2_l);
    cudaGetSymbolAddress((void**)&eB1, g_extB1);
    cudaGetSymbolAddress((void**)&eB2, g_extB2);
    cudaGetSymbolAddress((void**)&eB3, g_extB3);
    cudaGetSymbolAddress((void**)&eB4, g_extB4);
    cudaGetSymbolAddress((void**)&eB5, g_extB5);

    // fused prep: 1,671,168 items
    prep_k<<<6528, 256>>>(x, Wn, bn, We, be, Ws1, bs1, Ws2, bs2, Wh1, bh1, Wh2, bh2);

    // G1: T = x @ [Wn|We_a|We_b] + bcat   M=4096 K=128 N=768 (fp32 out)
    gemm_wmma<<<dim3(6, 64), 256>>>(xh, xl, FD, btc_h, btc_l, FD, eB1,
                                    T, 768, nullptr, nullptr, 0, FD, 0);

    hist_k<<<NE / 256, 256>>>(ei);
    scan_k<<<1, 1024>>>();
    fill_k<<<NE / 256, 256>>>(ei);
    misc_k<<<(NN * HD + NE) / 256, 256>>>(ei);   // buildB + node->bf16

    mean1_k<<<NN, 256>>>(out_node);
    mean2_k<<<NN, 256>>>();
    edge_k<<<(NE * 64) / 256, 256>>>(ei, out_edge);

    // G2: sh = relu(C[:, :512] @ Ws1 + bs1)  -> bf16 h/l
    gemm_wmma<<<dim3(2, 64), 256>>>(Chh, Cll, 768, bs1h, bs1l, 512, eB2,
                                    nullptr, 0, shh, shl, 256, 512, 1);
    // G3: out_sub = sh @ Ws2 + bs2 (fp32 out)
    gemm_wmma<<<dim3(2, 64), 256>>>(shh, shl, 256, bs2h, bs2l, 256, eB3,
                                    out_sub, 256, nullptr, nullptr, 0, 256, 0);
    // G4: nh = relu(C @ Wh1 + bh1) -> bf16 h/l
    gemm_wmma<<<dim3(2, 64), 256>>>(Chh, Cll, 768, bh1h, bh1l, 768, eB4,
                                    nullptr, 0, nhh, nhl, 256, 768, 1);
    // G5: out_nbh = nh @ Wh2 + bh2 (fp32 out)
    gemm_wmma<<<dim3(2, 64), 256>>>(nhh, nhl, 256, bh2h, bh2l, 256, eB5,
                                    out_nbh, 256, nullptr, nullptr, 0, 256, 0);
}

// round 7
// speedup vs baseline: 1.4691x; 1.1562x over previous
#include <cuda_runtime.h>
#include <cuda_bf16.h>
#include <cuda_pipeline.h>
#include <mma.h>
#include <stdint.h>

using namespace nvcuda;

#define NN 4096      // nodes
#define NE 65536     // edges
#define FD 128       // node feature dim
#define HD 256       // hidden dim

// ======================= scratch (device globals) =======================
__device__ __align__(16) float g_T[NN * 768];                 // [node | P | Q] stride 768

__device__ __align__(16) __nv_bfloat16 g_Tbh[NN * HD];        // node tokens bf16 (gather source)
__device__ __align__(16) __nv_bfloat16 g_xh[NN * FD],  g_xl[NN * FD];
__device__ __align__(16) __nv_bfloat16 g_Ch[NN * 768], g_Cl[NN * 768];   // [node|mean1|mean2] h/l
__device__ __align__(16) __nv_bfloat16 g_shh[NN * HD], g_shl[NN * HD];
__device__ __align__(16) __nv_bfloat16 g_nhh[NN * HD], g_nhl[NN * HD];
__device__ __align__(16) __nv_bfloat16 g_btc_h[768 * FD],  g_btc_l[768 * FD];   // [N=768][K=128]
__device__ __align__(16) __nv_bfloat16 g_bs1_h[HD * 512],  g_bs1_l[HD * 512];   // [256][512]
__device__ __align__(16) __nv_bfloat16 g_bs2_h[HD * HD],   g_bs2_l[HD * HD];
__device__ __align__(16) __nv_bfloat16 g_bh1_h[HD * 768],  g_bh1_l[HD * 768];
__device__ __align__(16) __nv_bfloat16 g_bh2_h[HD * HD],   g_bh2_l[HD * HD];

// bias-as-K-extension blocks
__device__ __align__(16) __nv_bfloat16 g_extA[128 * 32];      // ones in cols 0,1
__device__ __align__(16) __nv_bfloat16 g_extB1[768 * 32];     // [bn|be|0]
__device__ __align__(16) __nv_bfloat16 g_extB2[256 * 32];     // bs1
__device__ __align__(16) __nv_bfloat16 g_extB3[256 * 32];     // bs2
__device__ __align__(16) __nv_bfloat16 g_extB4[256 * 32];     // bh1
__device__ __align__(16) __nv_bfloat16 g_extB5[256 * 32];     // bh2

__device__ unsigned g_B[NN * 128];
__device__ int g_rowptr[NN + 1];
__device__ int g_colidx[NE];
__device__ int g_cnt[NN];
__device__ int g_cur[NN];

__device__ __forceinline__ void split1(float a, __nv_bfloat16& h, __nv_bfloat16& l) {
    h = __float2bfloat16(a);
    l = __float2bfloat16(a - __bfloat162float(h));
}

// ======================= fused prep (all weight/bias transforms + zeroing) =======================
// flat-index segments; total items = 1,671,168
__global__ __launch_bounds__(256)
void prep_k(const float* __restrict__ x,
            const float* __restrict__ Wn,  const float* __restrict__ bn,
            const float* __restrict__ We,  const float* __restrict__ be,
            const float* __restrict__ Ws1, const float* __restrict__ bs1,
            const float* __restrict__ Ws2, const float* __restrict__ bs2,
            const float* __restrict__ Wh1, const float* __restrict__ bh1,
            const float* __restrict__ Wh2, const float* __restrict__ bh2) {
    int idx = blockIdx.x * 256 + threadIdx.x;
    if (idx < 8192) {
        if (idx < 4096) { g_cnt[idx] = 0; g_cur[idx] = 0; }
        else {
            int i = idx - 4096;
            g_extA[i] = __float2bfloat16(((i & 31) < 2) ? 1.f : 0.f);
        }
        return;
    }
    idx -= 8192;
    if (idx < 524288) { g_B[idx] = 0u; return; }          // zero bitmasks
    idx -= 524288;
    if (idx < 524288) {                                    // x -> h/l
        __nv_bfloat16 h, l; split1(x[idx], h, l);
        g_xh[idx] = h; g_xl[idx] = l;
        return;
    }
    idx -= 524288;
    if (idx < 98304) {                                     // [Wn|We_a|We_b]^T -> btc
        int n = idx / FD, k = idx % FD;
        float v;
        if (n < 256)      v = Wn[k * 256 + n];
        else if (n < 512) v = We[k * 256 + (n - 256)];
        else              v = We[(128 + k) * 256 + (n - 512)];
        __nv_bfloat16 h, l; split1(v, h, l);
        g_btc_h[n * FD + k] = h; g_btc_l[n * FD + k] = l;
        return;
    }
    idx -= 98304;
    if (idx < 24576) {                                     // extB1 (bcat)
        int r = idx >> 5, k = idx & 31;
        float b = (r < 256) ? bn[r] : ((r < 512) ? be[r - 256] : 0.f);
        __nv_bfloat16 h, l; split1(b, h, l);
        g_extB1[idx] = (k == 0) ? h : ((k == 1) ? l : __float2bfloat16(0.f));
        return;
    }
    idx -= 24576;
    if (idx < 131072) {                                    // Ws1 [512][256] -> [256][512]
        int kk = idx >> 8, n = idx & 255;
        __nv_bfloat16 h, l; split1(Ws1[idx], h, l);
        g_bs1_h[n * 512 + kk] = h; g_bs1_l[n * 512 + kk] = l;
        return;
    }
    idx -= 131072;
    if (idx < 65536) {                                     // Ws2 [256][256]
        int kk = idx >> 8, n = idx & 255;
        __nv_bfloat16 h, l; split1(Ws2[idx], h, l);
        g_bs2_h[n * 256 + kk] = h; g_bs2_l[n * 256 + kk] = l;
        return;
    }
    idx -= 65536;
    if (idx < 196608) {                                    // Wh1 [768][256] -> [256][768]
        int kk = idx >> 8, n = idx & 255;
        __nv_bfloat16 h, l; split1(Wh1[idx], h, l);
        g_bh1_h[n * 768 + kk] = h; g_bh1_l[n * 768 + kk] = l;
        return;
    }
    idx -= 196608;
    if (idx < 65536) {                                     // Wh2 [256][256]
        int kk = idx >> 8, n = idx & 255;
        __nv_bfloat16 h, l; split1(Wh2[idx], h, l);
        g_bh2_h[n * 256 + kk] = h; g_bh2_l[n * 256 + kk] = l;
        return;
    }
    idx -= 65536;
    {
        const float* bias;
        __nv_bfloat16* dst;
        if (idx < 8192)       { bias = bs1; dst = g_extB2; }
        else if (idx < 16384) { bias = bs2; dst = g_extB3; idx -= 8192; }
        else if (idx < 24576) { bias = bh1; dst = g_extB4; idx -= 16384; }
        else                  { bias = bh2; dst = g_extB5; idx -= 24576; }
        int r = idx >> 5, k = idx & 31;
        __nv_bfloat16 h, l; split1(bias[r], h, l);
        dst[idx] = (k == 0) ? h : ((k == 1) ? l : __float2bfloat16(0.f));
    }
}

// ======================= wmma bf16x3 GEMM (batched by blockIdx.z) =======================
// C[M, Ntot] = A[M,K] @ Bt[Ntot,K]^T + bias (via ext-K), optional relu
// CTA tile 64(M) x 128(N), 8 warps (32x32 each), K chunks of 32, cp.async 2-stage.
// Output: Cf != null -> fp32; else bf16 h/l split (Oh/Ol).
#define AK 48   // smem K stride (bf16 elems)

struct GemmArgs {
    const __nv_bfloat16 *Ah, *Al, *Bh, *Bl, *extB;
    float* Cf;
    __nv_bfloat16 *Oh, *Ol;
    int lda, ldb, ldc, ldo, K, relu;
};

__device__ __forceinline__ void gemm_body(const GemmArgs& g) {
    __shared__ __align__(128) char smbuf[36864];
    auto As = reinterpret_cast<__nv_bfloat16(*)[64][AK]>(smbuf);           // [2][64][48]
    auto Bs = reinterpret_cast<__nv_bfloat16(*)[128][AK]>(smbuf + 12288);  // [2][128][48]

    int tid = threadIdx.x;
    int m0 = blockIdx.y * 64;
    int n0 = blockIdx.x * 128;
    int K = g.K;
    int nmain = (3 * K) >> 5;
    int nch = nmain + 1;

    int wid = tid >> 5;
    int wm = wid & 1;
    int wn = wid >> 1;

    wmma::fragment<wmma::accumulator, 16, 16, 16, float> acc[2][2];
#pragma unroll
    for (int fm = 0; fm < 2; fm++)
#pragma unroll
        for (int fn = 0; fn < 2; fn++)
            wmma::fill_fragment(acc[fm][fn], 0.f);

    auto issue = [&](int c, int s) {
        const __nv_bfloat16 *Asrc, *Bsrc;
        int alda, blda;
        if (c < nmain) {
            int kb = c << 5;
            int seg = kb / K;
            int off = kb - seg * K;
            Asrc = ((seg == 1) ? g.Al : g.Ah) + (size_t)m0 * g.lda + off; alda = g.lda;
            Bsrc = ((seg == 2) ? g.Bl : g.Bh) + (size_t)n0 * g.ldb + off; blda = g.ldb;
        } else {
            Asrc = g_extA;                   alda = 32;
            Bsrc = g.extB + (size_t)n0 * 32; blda = 32;
        }
        int r = tid >> 2, kq = (tid & 3) * 8;
        __pipeline_memcpy_async(&As[s][r][kq],      Asrc + (size_t)r * alda + kq, 16);
        __pipeline_memcpy_async(&Bs[s][r][kq],      Bsrc + (size_t)r * blda + kq, 16);
        __pipeline_memcpy_async(&Bs[s][r + 64][kq], Bsrc + (size_t)(r + 64) * blda + kq, 16);
    };

    issue(0, 0);
    __pipeline_commit();

    for (int c = 0; c < nch; c++) {
        if (c + 1 < nch) {
            issue(c + 1, (c + 1) & 1);
            __pipeline_commit();
            __pipeline_wait_prior(1);
        } else {
            __pipeline_wait_prior(0);
        }
        __syncthreads();
        int s = c & 1;
#pragma unroll
        for (int ks = 0; ks < 32; ks += 16) {
            wmma::fragment<wmma::matrix_a, 16, 16, 16, __nv_bfloat16, wmma::row_major> a[2];
            wmma::fragment<wmma::matrix_b, 16, 16, 16, __nv_bfloat16, wmma::col_major> b[2];
#pragma unroll
            for (int fm = 0; fm < 2; fm++)
                wmma::load_matrix_sync(a[fm], &As[s][wm * 32 + fm * 16][ks], AK);
#pragma unroll
            for (int fn = 0; fn < 2; fn++)
                wmma::load_matrix_sync(b[fn], &Bs[s][wn * 32 + fn * 16][ks], AK);
#pragma unroll
            for (int fm = 0; fm < 2; fm++)
#pragma unroll
                for (int fn = 0; fn < 2; fn++)
                    wmma::mma_sync(acc[fm][fn], a[fm], b[fn], acc[fm][fn]);
        }
        __syncthreads();
    }

    if (g.relu) {
#pragma unroll
        for (int fm = 0; fm < 2; fm++)
#pragma unroll
            for (int fn = 0; fn < 2; fn++)
#pragma unroll
                for (int i = 0; i < acc[fm][fn].num_elements; i++)
                    acc[fm][fn].x[i] = fmaxf(acc[fm][fn].x[i], 0.f);
    }

    if (g.Cf) {
#pragma unroll
        for (int fm = 0; fm < 2; fm++)
#pragma unroll
            for (int fn = 0; fn < 2; fn++)
                wmma::store_matrix_sync(
                    &g.Cf[(size_t)(m0 + wm * 32 + fm * 16) * g.ldc + n0 + wn * 32 + fn * 16],
                    acc[fm][fn], g.ldc, wmma::mem_row_major);
    } else {
        float* epi = (float*)smbuf;   // [64][132] = 33792B
#pragma unroll
        for (int fm = 0; fm < 2; fm++)
#pragma unroll
            for (int fn = 0; fn < 2; fn++)
                wmma::store_matrix_sync(
                    &epi[(wm * 32 + fm * 16) * 132 + wn * 32 + fn * 16],
                    acc[fm][fn], 132, wmma::mem_row_major);
        __syncthreads();
        for (int idx = tid; idx < 64 * 128; idx += 256) {
            int row = idx >> 7, col = idx & 127;
            float v = epi[row * 132 + col];
            __nv_bfloat16 h, l; split1(v, h, l);
            size_t o = (size_t)(m0 + row) * g.ldo + n0 + col;
            g.Oh[o] = h; g.Ol[o] = l;
        }
    }
}

__global__ __launch_bounds__(256)
void gemm_wmma1(GemmArgs a0) { gemm_body(a0); }

__global__ __launch_bounds__(256)
void gemm_wmma2(GemmArgs a0, GemmArgs a1) { gemm_body(blockIdx.z ? a1 : a0); }

// ======================= CSR build =======================
__global__ void hist_k(const int* __restrict__ ei) {
    int e = blockIdx.x * blockDim.x + threadIdx.x;
    if (e < NE) atomicAdd(&g_cnt[ei[e]], 1);
}

__global__ void scan_k() {
    __shared__ int s[1024];
    int t = threadIdx.x;
    int b = t * 4;
    int c0 = g_cnt[b], c1 = g_cnt[b + 1], c2 = g_cnt[b + 2], c3 = g_cnt[b + 3];
    int sum = c0 + c1 + c2 + c3;
    s[t] = sum;
    __syncthreads();
    for (int off = 1; off < 1024; off <<= 1) {
        int v = (t >= off) ? s[t - off] : 0;
        __syncthreads();
        s[t] += v;
        __syncthreads();
    }
    int excl = s[t] - sum;
    g_rowptr[b]     = excl;
    g_rowptr[b + 1] = excl + c0;
    g_rowptr[b + 2] = excl + c0 + c1;
    g_rowptr[b + 3] = excl + c0 + c1 + c2;
    if (t == 1023) g_rowptr[NN] = excl + sum;
}

// ======================= fused: fill colidx + bitmask + node->bf16 =======================
// flat items: [0,NE)=fill, [NE,2NE)=bitmask, [2NE, 2NE+NN*HD)=Tbh
__global__ __launch_bounds__(256)
void fillmisc_k(const int* __restrict__ ei) {
    int idx = blockIdx.x * 256 + threadIdx.x;
    if (idx < NE) {
        int r = ei[idx];
        int pos = g_rowptr[r] + atomicAdd(&g_cur[r], 1);
        g_colidx[pos] = ei[NE + idx];
        return;
    }
    idx -= NE;
    if (idx < NE) {
        int r = ei[idx], c = ei[NE + idx];
        atomicOr(&g_B[(unsigned)r * 128u + (c >> 5)], 1u << (c & 31));
        return;
    }
    idx -= NE;
    if (idx < NN * HD) {
        int row = idx >> 8, col = idx & 255;
        g_Tbh[idx] = __float2bfloat16(g_T[(size_t)row * 768 + col]);
    }
}

// ======================= mean1 + node copy + bf16 h/l writes =======================
__global__ __launch_bounds__(256)
void mean1_k(float* __restrict__ out_node) {
    int i = blockIdx.x, h = threadIdx.x;
    int s = g_rowptr[i], e = g_rowptr[i + 1];
    float a0 = 0.f, a1 = 0.f, a2 = 0.f, a3 = 0.f;
    int p = s;
    for (; p + 4 <= e; p += 4) {
        int j0 = g_colidx[p], j1 = g_colidx[p + 1], j2 = g_colidx[p + 2], j3 = g_colidx[p + 3];
        a0 += g_T[(size_t)j0 * 768 + h];
        a1 += g_T[(size_t)j1 * 768 + h];
        a2 += g_T[(size_t)j2 * 768 + h];
        a3 += g_T[(size_t)j3 * 768 + h];
    }
    for (; p < e; p++) a0 += g_T[(size_t)g_colidx[p] * 768 + h];
    float acc = (a0 + a1) + (a2 + a3);
    int deg = e - s;
    float m = deg > 0 ? acc / (float)deg : 0.f;
    float nd = g_T[(size_t)i * 768 + h];
    out_node[(size_t)i * 256 + h] = nd;
    __nv_bfloat16 hh, ll;
    split1(nd, hh, ll);
    g_Ch[(size_t)i * 768 + h] = hh; g_Cl[(size_t)i * 768 + h] = ll;
    split1(m, hh, ll);
    g_Ch[(size_t)i * 768 + 256 + h] = hh; g_Cl[(size_t)i * 768 + 256 + h] = ll;
}

// ======================= mean2: dedup'd 2-hop mean (bf16 gather) =======================
__global__ __launch_bounds__(256)
void mean2_k() {
    __shared__ unsigned rm[128];
    __shared__ int sc[128];
    __shared__ float2 part[128];
    __shared__ unsigned short list[NN];
    int i = blockIdx.x, t = threadIdx.x;
    int s = g_rowptr[i], e = g_rowptr[i + 1];

    if (t < 128) {
        unsigned m = 0u;
        for (int p = s; p < e; p++) {
            int k = g_colidx[p];
            m |= g_B[(unsigned)k * 128u + t];
        }
        if (t == (i >> 5)) m &= ~(1u << (i & 31));
        rm[t] = m;
        sc[t] = __popc(m);
    }
    __syncthreads();
    for (int off = 1; off < 128; off <<= 1) {
        int v = 0;
        if (t < 128 && t >= off) v = sc[t - off];
        __syncthreads();
        if (t < 128) sc[t] += v;
        __syncthreads();
    }
    if (t < 128) {
        unsigned m = rm[t];
        int o = sc[t] - __popc(m);
        int base = t << 5;
        while (m) {
            int b = __ffs(m) - 1;
            m &= m - 1;
            list[o++] = (unsigned short)(base + b);
        }
    }
    __syncthreads();
    int cnt = sc[127];

    const unsigned* Tb = (const unsigned*)g_Tbh;   // [NN][128] words
    int p = t & 127, hh = t >> 7;
    float ax = 0.f, ay = 0.f, bx = 0.f, by = 0.f;
    int r = hh;
    for (; r + 2 < cnt; r += 4) {
        unsigned w0 = Tb[(unsigned)list[r] * 128u + p];
        unsigned w1 = Tb[(unsigned)list[r + 2] * 128u + p];
        __nv_bfloat162 v0 = *(__nv_bfloat162*)&w0;
        __nv_bfloat162 v1 = *(__nv_bfloat162*)&w1;
        ax += __bfloat162float(v0.x); ay += __bfloat162float(v0.y);
        bx += __bfloat162float(v1.x); by += __bfloat162float(v1.y);
    }
    for (; r < cnt; r += 2) {
        unsigned w = Tb[(unsigned)list[r] * 128u + p];
        __nv_bfloat162 v = *(__nv_bfloat162*)&w;
        ax += __bfloat162float(v.x); ay += __bfloat162float(v.y);
    }
    float sx = ax + bx, sy = ay + by;
    if (hh) part[p] = make_float2(sx, sy);
    __syncthreads();
    if (!hh) {
        sx += part[p].x; sy += part[p].y;
        float m0v = cnt > 0 ? sx / (float)cnt : 0.f;
        float m1v = cnt > 0 ? sy / (float)cnt : 0.f;
        __nv_bfloat16 h0, l0, h1, l1;
        split1(m0v, h0, l0);
        split1(m1v, h1, l1);
        __nv_bfloat162 ph; ph.x = h0; ph.y = h1;
        __nv_bfloat162 pl; pl.x = l0; pl.y = l1;
        *(__nv_bfloat162*)&g_Ch[(size_t)i * 768 + 512 + 2 * p] = ph;
        *(__nv_bfloat162*)&g_Cl[(size_t)i * 768 + 512 + 2 * p] = pl;
    }
}

// ======================= edge assembly =======================
__global__ __launch_bounds__(256)
void edge_k(const int* __restrict__ ei, float* __restrict__ out_edge) {
    int gid = blockIdx.x * 256 + threadIdx.x;
    int e = gid >> 6;
    int c = (gid & 63) << 2;
    int r = ei[e], cl = ei[NE + e];
    float4 p = *(const float4*)&g_T[(size_t)r * 768 + 256 + c];
    float4 q = *(const float4*)&g_T[(size_t)cl * 768 + 512 + c];
    float4 o;
    o.x = p.x + q.x; o.y = p.y + q.y; o.z = p.z + q.z; o.w = p.w + q.w;
    *(float4*)&out_edge[(size_t)e * 256 + c] = o;
}

// ======================= launch =======================
extern "C" void kernel_launch(void* const* d_in, const int* in_sizes, int n_in,
                              void* d_out, int out_size) {
    const float* x   = (const float*)d_in[0];
    const int*   ei  = (const int*)  d_in[1];
    const float* Wn  = (const float*)d_in[2];
    const float* bn  = (const float*)d_in[3];
    const float* We  = (const float*)d_in[4];
    const float* be  = (const float*)d_in[5];
    const float* Ws1 = (const float*)d_in[6];
    const float* bs1 = (const float*)d_in[7];
    const float* Ws2 = (const float*)d_in[8];
    const float* bs2 = (const float*)d_in[9];
    const float* Wh1 = (const float*)d_in[10];
    const float* bh1 = (const float*)d_in[11];
    const float* Wh2 = (const float*)d_in[12];
    const float* bh2 = (const float*)d_in[13];

    float* out      = (float*)d_out;
    float* out_node = out;
    float* out_edge = out_node + (size_t)NN * HD;
    float* out_sub  = out_edge + (size_t)NE * HD;
    float* out_nbh  = out_sub  + (size_t)NN * HD;

    float* T;
    cudaGetSymbolAddress((void**)&T, g_T);
    __nv_bfloat16 *xh, *xl, *Chh, *Cll, *shh, *shl, *nhh, *nhl;
    __nv_bfloat16 *btc_h, *btc_l, *bs1h, *bs1l, *bs2h, *bs2l, *bh1h, *bh1l, *bh2h, *bh2l;
    __nv_bfloat16 *eB1, *eB2, *eB3, *eB4, *eB5;
    cudaGetSymbolAddress((void**)&xh, g_xh);   cudaGetSymbolAddress((void**)&xl, g_xl);
    cudaGetSymbolAddress((void**)&Chh, g_Ch);  cudaGetSymbolAddress((void**)&Cll, g_Cl);
    cudaGetSymbolAddress((void**)&shh, g_shh); cudaGetSymbolAddress((void**)&shl, g_shl);
    cudaGetSymbolAddress((void**)&nhh, g_nhh); cudaGetSymbolAddress((void**)&nhl, g_nhl);
    cudaGetSymbolAddress((void**)&btc_h, g_btc_h); cudaGetSymbolAddress((void**)&btc_l, g_btc_l);
    cudaGetSymbolAddress((void**)&bs1h, g_bs1_h);  cudaGetSymbolAddress((void**)&bs1l, g_bs1_l);
    cudaGetSymbolAddress((void**)&bs2h, g_bs2_h);  cudaGetSymbolAddress((void**)&bs2l, g_bs2_l);
    cudaGetSymbolAddress((void**)&bh1h, g_bh1_h);  cudaGetSymbolAddress((void**)&bh1l, g_bh1_l);
    cudaGetSymbolAddress((void**)&bh2h, g_bh2_h);  cudaGetSymbolAddress((void**)&bh2l, g_bh2_l);
    cudaGetSymbolAddress((void**)&eB1, g_extB1);
    cudaGetSymbolAddress((void**)&eB2, g_extB2);
    cudaGetSymbolAddress((void**)&eB3, g_extB3);
    cudaGetSymbolAddress((void**)&eB4, g_extB4);
    cudaGetSymbolAddress((void**)&eB5, g_extB5);

    // fused prep: 1,671,168 items
    prep_k<<<6528, 256>>>(x, Wn, bn, We, be, Ws1, bs1, Ws2, bs2, Wh1, bh1, Wh2, bh2);

    // G1: T = x @ [Wn|We_a|We_b] + bcat   M=4096 K=128 N=768 (fp32 out)
    {
        GemmArgs a1 = { xh, xl, btc_h, btc_l, eB1, T, nullptr, nullptr,
                        FD, FD, 768, 0, FD, 0 };
        gemm_wmma1<<<dim3(6, 64), 256>>>(a1);
    }

    hist_k<<<NE / 256, 256>>>(ei);
    scan_k<<<1, 1024>>>();
    fillmisc_k<<<(2 * NE + NN * HD) / 256, 256>>>(ei);   // fill + bitmask + node->bf16

    mean1_k<<<NN, 256>>>(out_node);
    mean2_k<<<NN, 256>>>();
    edge_k<<<(NE * 64) / 256, 256>>>(ei, out_edge);

    // batched {G2, G4}: both read C, write sh / nh (bf16 h/l, relu)
    {
        GemmArgs a2 = { Chh, Cll, bs1h, bs1l, eB2, nullptr, shh, shl,
                        768, 512, 0, 256, 512, 1 };
        GemmArgs a4 = { Chh, Cll, bh1h, bh1l, eB4, nullptr, nhh, nhl,
                        768, 768, 0, 256, 768, 1 };
        gemm_wmma2<<<dim3(2, 64, 2), 256>>>(a2, a4);
    }
    // batched {G3, G5}: sh@Ws2 -> out_sub, nh@Wh2 -> out_nbh (fp32)
    {
        GemmArgs a3 = { shh, shl, bs2h, bs2l, eB3, out_sub, nullptr, nullptr,
                        256, 256, 256, 0, 256, 0 };
        GemmArgs a5 = { nhh, nhl, bh2h, bh2l, eB5, out_nbh, nullptr, nullptr,
                        256, 256, 256, 0, 256, 0 };
        gemm_wmma2<<<dim3(2, 64, 2), 256>>>(a3, a5);
    }
}

// round 9
// speedup vs baseline: 1.5400x; 1.0483x over previous
#include <cuda_runtime.h>
#include <cuda_bf16.h>
#include <cuda_pipeline.h>
#include <mma.h>
#include <stdint.h>

using namespace nvcuda;

#define NN 4096      // nodes
#define NE 65536     // edges
#define FD 128       // node feature dim
#define HD 256       // hidden dim

// ======================= scratch (device globals) =======================
__device__ __align__(16) float g_T[NN * 768];                 // [node | P | Q] stride 768

__device__ __align__(16) __nv_bfloat16 g_Tbh[NN * HD];        // node tokens bf16 (gather source)
__device__ __align__(16) __nv_bfloat16 g_xh[NN * FD],  g_xl[NN * FD];
__device__ __align__(16) __nv_bfloat16 g_Ch[NN * 768], g_Cl[NN * 768];   // [node|mean1|mean2] h/l
__device__ __align__(16) __nv_bfloat16 g_shh[NN * HD], g_shl[NN * HD];
__device__ __align__(16) __nv_bfloat16 g_nhh[NN * HD], g_nhl[NN * HD];
__device__ __align__(16) __nv_bfloat16 g_btc_h[768 * FD],  g_btc_l[768 * FD];   // [N=768][K=128]
__device__ __align__(16) __nv_bfloat16 g_bs1_h[HD * 512],  g_bs1_l[HD * 512];   // [256][512]
__device__ __align__(16) __nv_bfloat16 g_bs2_h[HD * HD],   g_bs2_l[HD * HD];
__device__ __align__(16) __nv_bfloat16 g_bh1_h[HD * 768],  g_bh1_l[HD * 768];
__device__ __align__(16) __nv_bfloat16 g_bh2_h[HD * HD],   g_bh2_l[HD * HD];

// bias-as-K-extension blocks
__device__ __align__(16) __nv_bfloat16 g_extA[128 * 32];      // ones in cols 0,1
__device__ __align__(16) __nv_bfloat16 g_extB1[768 * 32];     // [bn|be|0]
__device__ __align__(16) __nv_bfloat16 g_extB2[256 * 32];     // bs1
__device__ __align__(16) __nv_bfloat16 g_extB3[256 * 32];     // bs2
__device__ __align__(16) __nv_bfloat16 g_extB4[256 * 32];     // bh1
__device__ __align__(16) __nv_bfloat16 g_extB5[256 * 32];     // bh2

__device__ unsigned g_B[NN * 128];
__device__ int g_rowptr[NN + 1];
__device__ int g_colidx[NE];
__device__ int g_cnt[NN];     // zeroed by scan_k tail for next replay (BSS-zero on first call)
__device__ int g_cur[NN];     // same

__device__ __forceinline__ void split1(float a, __nv_bfloat16& h, __nv_bfloat16& l) {
    h = __float2bfloat16(a);
    l = __float2bfloat16(a - __bfloat162float(h));
}

// ======================= fused prep (weights/bias transforms + zeroing + hist) ==============
// flat segments; total = 1,732,608 = 6768 * 256
__global__ __launch_bounds__(256)
void prep_k(const float* __restrict__ x, const int* __restrict__ ei,
            const float* __restrict__ Wn,  const float* __restrict__ bn,
            const float* __restrict__ We,  const float* __restrict__ be,
            const float* __restrict__ Ws1, const float* __restrict__ bs1,
            const float* __restrict__ Ws2, const float* __restrict__ bs2,
            const float* __restrict__ Wh1, const float* __restrict__ bh1,
            const float* __restrict__ Wh2, const float* __restrict__ bh2) {
    int idx = blockIdx.x * 256 + threadIdx.x;
    if (idx < 65536) {                                     // hist (cnt starts at 0)
        atomicAdd(&g_cnt[ei[idx]], 1);
        return;
    }
    idx -= 65536;
    if (idx < 4096) {                                      // extA
        g_extA[idx] = __float2bfloat16(((idx & 31) < 2) ? 1.f : 0.f);
        return;
    }
    idx -= 4096;
    if (idx < 524288) { g_B[idx] = 0u; return; }           // zero bitmasks
    idx -= 524288;
    if (idx < 524288) {                                    // x -> h/l
        __nv_bfloat16 h, l; split1(x[idx], h, l);
        g_xh[idx] = h; g_xl[idx] = l;
        return;
    }
    idx -= 524288;
    if (idx < 98304) {                                     // [Wn|We_a|We_b]^T -> btc
        int n = idx / FD, k = idx % FD;
        float v;
        if (n < 256)      v = Wn[k * 256 + n];
        else if (n < 512) v = We[k * 256 + (n - 256)];
        else              v = We[(128 + k) * 256 + (n - 512)];
        __nv_bfloat16 h, l; split1(v, h, l);
        g_btc_h[n * FD + k] = h; g_btc_l[n * FD + k] = l;
        return;
    }
    idx -= 98304;
    if (idx < 24576) {                                     // extB1 (bcat)
        int r = idx >> 5, k = idx & 31;
        float b = (r < 256) ? bn[r] : ((r < 512) ? be[r - 256] : 0.f);
        __nv_bfloat16 h, l; split1(b, h, l);
        g_extB1[idx] = (k == 0) ? h : ((k == 1) ? l : __float2bfloat16(0.f));
        return;
    }
    idx -= 24576;
    if (idx < 131072) {                                    // Ws1 [512][256] -> [256][512]
        int kk = idx >> 8, n = idx & 255;
        __nv_bfloat16 h, l; split1(Ws1[idx], h, l);
        g_bs1_h[n * 512 + kk] = h; g_bs1_l[n * 512 + kk] = l;
        return;
    }
    idx -= 131072;
    if (idx < 65536) {                                     // Ws2 [256][256]
        int kk = idx >> 8, n = idx & 255;
        __nv_bfloat16 h, l; split1(Ws2[idx], h, l);
        g_bs2_h[n * 256 + kk] = h; g_bs2_l[n * 256 + kk] = l;
        return;
    }
    idx -= 65536;
    if (idx < 196608) {                                    // Wh1 [768][256] -> [256][768]
        int kk = idx >> 8, n = idx & 255;
        __nv_bfloat16 h, l; split1(Wh1[idx], h, l);
        g_bh1_h[n * 768 + kk] = h; g_bh1_l[n * 768 + kk] = l;
        return;
    }
    idx -= 196608;
    if (idx < 65536) {                                     // Wh2 [256][256]
        int kk = idx >> 8, n = idx & 255;
        __nv_bfloat16 h, l; split1(Wh2[idx], h, l);
        g_bh2_h[n * 256 + kk] = h; g_bh2_l[n * 256 + kk] = l;
        return;
    }
    idx -= 65536;
    {
        const float* bias;
        __nv_bfloat16* dst;
        if (idx < 8192)       { bias = bs1; dst = g_extB2; }
        else if (idx < 16384) { bias = bs2; dst = g_extB3; idx -= 8192; }
        else if (idx < 24576) { bias = bh1; dst = g_extB4; idx -= 16384; }
        else                  { bias = bh2; dst = g_extB5; idx -= 24576; }
        int r = idx >> 5, k = idx & 31;
        __nv_bfloat16 h, l; split1(bias[r], h, l);
        dst[idx] = (k == 0) ? h : ((k == 1) ? l : __float2bfloat16(0.f));
    }
}

// ======================= wmma bf16x3 GEMM (batched by blockIdx.z) =======================
#define AK 48   // smem K stride (bf16 elems)

struct GemmArgs {
    const __nv_bfloat16 *Ah, *Al, *Bh, *Bl, *extB;
    float* Cf;
    __nv_bfloat16 *Oh, *Ol;
    int lda, ldb, ldc, ldo, K, relu;
};

__device__ __forceinline__ void gemm_body(const GemmArgs& g) {
    __shared__ __align__(128) char smbuf[36864];
    auto As = reinterpret_cast<__nv_bfloat16(*)[64][AK]>(smbuf);           // [2][64][48]
    auto Bs = reinterpret_cast<__nv_bfloat16(*)[128][AK]>(smbuf + 12288);  // [2][128][48]

    int tid = threadIdx.x;
    int m0 = blockIdx.y * 64;
    int n0 = blockIdx.x * 128;
    int K = g.K;
    int nmain = (3 * K) >> 5;
    int nch = nmain + 1;

    int wid = tid >> 5;
    int wm = wid & 1;
    int wn = wid >> 1;

    wmma::fragment<wmma::accumulator, 16, 16, 16, float> acc[2][2];
#pragma unroll
    for (int fm = 0; fm < 2; fm++)
#pragma unroll
        for (int fn = 0; fn < 2; fn++)
            wmma::fill_fragment(acc[fm][fn], 0.f);

    auto issue = [&](int c, int s) {
        const __nv_bfloat16 *Asrc, *Bsrc;
        int alda, blda;
        if (c < nmain) {
            int kb = c << 5;
            int seg = kb / K;
            int off = kb - seg * K;
            Asrc = ((seg == 1) ? g.Al : g.Ah) + (size_t)m0 * g.lda + off; alda = g.lda;
            Bsrc = ((seg == 2) ? g.Bl : g.Bh) + (size_t)n0 * g.ldb + off; blda = g.ldb;
        } else {
            Asrc = g_extA;                   alda = 32;
            Bsrc = g.extB + (size_t)n0 * 32; blda = 32;
        }
        int r = tid >> 2, kq = (tid & 3) * 8;
        __pipeline_memcpy_async(&As[s][r][kq],      Asrc + (size_t)r * alda + kq, 16);
        __pipeline_memcpy_async(&Bs[s][r][kq],      Bsrc + (size_t)r * blda + kq, 16);
        __pipeline_memcpy_async(&Bs[s][r + 64][kq], Bsrc + (size_t)(r + 64) * blda + kq, 16);
    };

    issue(0, 0);
    __pipeline_commit();

    for (int c = 0; c < nch; c++) {
        if (c + 1 < nch) {
            issue(c + 1, (c + 1) & 1);
            __pipeline_commit();
            __pipeline_wait_prior(1);
        } else {
            __pipeline_wait_prior(0);
        }
        __syncthreads();
        int s = c & 1;
#pragma unroll
        for (int ks = 0; ks < 32; ks += 16) {
            wmma::fragment<wmma::matrix_a, 16, 16, 16, __nv_bfloat16, wmma::row_major> a[2];
            wmma::fragment<wmma::matrix_b, 16, 16, 16, __nv_bfloat16, wmma::col_major> b[2];
#pragma unroll
            for (int fm = 0; fm < 2; fm++)
                wmma::load_matrix_sync(a[fm], &As[s][wm * 32 + fm * 16][ks], AK);
#pragma unroll
            for (int fn = 0; fn < 2; fn++)
                wmma::load_matrix_sync(b[fn], &Bs[s][wn * 32 + fn * 16][ks], AK);
#pragma unroll
            for (int fm = 0; fm < 2; fm++)
#pragma unroll
                for (int fn = 0; fn < 2; fn++)
                    wmma::mma_sync(acc[fm][fn], a[fm], b[fn], acc[fm][fn]);
        }
        __syncthreads();
    }

    if (g.relu) {
#pragma unroll
        for (int fm = 0; fm < 2; fm++)
#pragma unroll
            for (int fn = 0; fn < 2; fn++)
#pragma unroll
                for (int i = 0; i < acc[fm][fn].num_elements; i++)
                    acc[fm][fn].x[i] = fmaxf(acc[fm][fn].x[i], 0.f);
    }

    if (g.Cf) {
#pragma unroll
        for (int fm = 0; fm < 2; fm++)
#pragma unroll
            for (int fn = 0; fn < 2; fn++)
                wmma::store_matrix_sync(
                    &g.Cf[(size_t)(m0 + wm * 32 + fm * 16) * g.ldc + n0 + wn * 32 + fn * 16],
                    acc[fm][fn], g.ldc, wmma::mem_row_major);
    } else {
        float* epi = (float*)smbuf;   // [64][132] = 33792B
#pragma unroll
        for (int fm = 0; fm < 2; fm++)
#pragma unroll
            for (int fn = 0; fn < 2; fn++)
                wmma::store_matrix_sync(
                    &epi[(wm * 32 + fm * 16) * 132 + wn * 32 + fn * 16],
                    acc[fm][fn], 132, wmma::mem_row_major);
        __syncthreads();
        for (int idx = tid; idx < 64 * 128; idx += 256) {
            int row = idx >> 7, col = idx & 127;
            float v = epi[row * 132 + col];
            __nv_bfloat16 h, l; split1(v, h, l);
            size_t o = (size_t)(m0 + row) * g.ldo + n0 + col;
            g.Oh[o] = h; g.Ol[o] = l;
        }
    }
}

__global__ __launch_bounds__(256)
void gemm_wmma1(GemmArgs a0) { gemm_body(a0); }

__global__ __launch_bounds__(256)
void gemm_wmma2(GemmArgs a0, GemmArgs a1) { gemm_body(blockIdx.z ? a1 : a0); }

// ======================= scan (+ zero cnt/cur for next replay) =======================
__global__ void scan_k() {
    __shared__ int s[1024];
    int t = threadIdx.x;
    int b = t * 4;
    int c0 = g_cnt[b], c1 = g_cnt[b + 1], c2 = g_cnt[b + 2], c3 = g_cnt[b + 3];
    int sum = c0 + c1 + c2 + c3;
    s[t] = sum;
    __syncthreads();
    for (int off = 1; off < 1024; off <<= 1) {
        int v = (t >= off) ? s[t - off] : 0;
        __syncthreads();
        s[t] += v;
        __syncthreads();
    }
    int excl = s[t] - sum;
    g_rowptr[b]     = excl;
    g_rowptr[b + 1] = excl + c0;
    g_rowptr[b + 2] = excl + c0 + c1;
    g_rowptr[b + 3] = excl + c0 + c1 + c2;
    if (t == 1023) g_rowptr[NN] = excl + sum;
    // reset for next graph replay (deterministic: consumed values already latched)
    g_cnt[b] = 0; g_cnt[b + 1] = 0; g_cnt[b + 2] = 0; g_cnt[b + 3] = 0;
    g_cur[b] = 0; g_cur[b + 1] = 0; g_cur[b + 2] = 0; g_cur[b + 3] = 0;
}

// ======================= fused: fill colidx + bitmask + node->bf16 =======================
__global__ __launch_bounds__(256)
void fillmisc_k(const int* __restrict__ ei) {
    int idx = blockIdx.x * 256 + threadIdx.x;
    if (idx < NE) {
        int r = ei[idx];
        int pos = g_rowptr[r] + atomicAdd(&g_cur[r], 1);
        g_colidx[pos] = ei[NE + idx];
        return;
    }
    idx -= NE;
    if (idx < NE) {
        int r = ei[idx], c = ei[NE + idx];
        atomicOr(&g_B[(unsigned)r * 128u + (c >> 5)], 1u << (c & 31));
        return;
    }
    idx -= NE;
    if (idx < NN * HD) {
        int row = idx >> 8, col = idx & 255;
        g_Tbh[idx] = __float2bfloat16(g_T[(size_t)row * 768 + col]);
    }
}

// ======================= fused graph kernel: mean2 | mean1 | edge =======================
// blocks [0,4096): mean2(i)   [4096,8192): mean1(i-4096)   [8192,24576): edge
__global__ __launch_bounds__(256)
void graph_k(const int* __restrict__ ei,
             float* __restrict__ out_node, float* __restrict__ out_edge) {
    __shared__ unsigned rm[128];
    __shared__ int sc[128];
    __shared__ float2 part[128];
    __shared__ unsigned short list[NN];

    int bid = blockIdx.x;
    int t = threadIdx.x;

    if (bid < NN) {
        // ---------------- mean2 ----------------
        int i = bid;
        int s = g_rowptr[i], e = g_rowptr[i + 1];
        if (t < 128) {
            unsigned m = 0u;
            for (int p = s; p < e; p++) {
                int k = g_colidx[p];
                m |= g_B[(unsigned)k * 128u + t];
            }
            if (t == (i >> 5)) m &= ~(1u << (i & 31));
            rm[t] = m;
            sc[t] = __popc(m);
        }
        __syncthreads();
        for (int off = 1; off < 128; off <<= 1) {
            int v = 0;
            if (t < 128 && t >= off) v = sc[t - off];
            __syncthreads();
            if (t < 128) sc[t] += v;
            __syncthreads();
        }
        if (t < 128) {
            unsigned m = rm[t];
            int o = sc[t] - __popc(m);
            int base = t << 5;
            while (m) {
                int b = __ffs(m) - 1;
                m &= m - 1;
                list[o++] = (unsigned short)(base + b);
            }
        }
        __syncthreads();
        int cnt = sc[127];

        const unsigned* Tb = (const unsigned*)g_Tbh;   // [NN][128] words
        int p = t & 127, hh = t >> 7;
        float ax = 0.f, ay = 0.f, bx = 0.f, by = 0.f;
        int r = hh;
        for (; r + 2 < cnt; r += 4) {
            unsigned w0 = Tb[(unsigned)list[r] * 128u + p];
            unsigned w1 = Tb[(unsigned)list[r + 2] * 128u + p];
            __nv_bfloat162 v0 = *(__nv_bfloat162*)&w0;
            __nv_bfloat162 v1 = *(__nv_bfloat162*)&w1;
            ax += __bfloat162float(v0.x); ay += __bfloat162float(v0.y);
            bx += __bfloat162float(v1.x); by += __bfloat162float(v1.y);
        }
        for (; r < cnt; r += 2) {
            unsigned w = Tb[(unsigned)list[r] * 128u + p];
            __nv_bfloat162 v = *(__nv_bfloat162*)&w;
            ax += __bfloat162float(v.x); ay += __bfloat162float(v.y);
        }
        float sx = ax + bx, sy = ay + by;
        if (hh) part[p] = make_float2(sx, sy);
        __syncthreads();
        if (!hh) {
            sx += part[p].x; sy += part[p].y;
            float m0v = cnt > 0 ? sx / (float)cnt : 0.f;
            float m1v = cnt > 0 ? sy / (float)cnt : 0.f;
            __nv_bfloat16 h0, l0, h1, l1;
            split1(m0v, h0, l0);
            split1(m1v, h1, l1);
            __nv_bfloat162 ph; ph.x = h0; ph.y = h1;
            __nv_bfloat162 pl; pl.x = l0; pl.y = l1;
            *(__nv_bfloat162*)&g_Ch[(size_t)i * 768 + 512 + 2 * p] = ph;
            *(__nv_bfloat162*)&g_Cl[(size_t)i * 768 + 512 + 2 * p] = pl;
        }
    } else if (bid < 2 * NN) {
        // ---------------- mean1 ----------------
        int i = bid - NN;
        int h = t;
        int s = g_rowptr[i], e = g_rowptr[i + 1];
        float a0 = 0.f, a1 = 0.f, a2 = 0.f, a3 = 0.f;
        int p = s;
        for (; p + 4 <= e; p += 4) {
            int j0 = g_colidx[p], j1 = g_colidx[p + 1], j2 = g_colidx[p + 2], j3 = g_colidx[p + 3];
            a0 += g_T[(size_t)j0 * 768 + h];
            a1 += g_T[(size_t)j1 * 768 + h];
            a2 += g_T[(size_t)j2 * 768 + h];
            a3 += g_T[(size_t)j3 * 768 + h];
        }
        for (; p < e; p++) a0 += g_T[(size_t)g_colidx[p] * 768 + h];
        float acc = (a0 + a1) + (a2 + a3);
        int deg = e - s;
        float m = deg > 0 ? acc / (float)deg : 0.f;
        float nd = g_T[(size_t)i * 768 + h];
        out_node[(size_t)i * 256 + h] = nd;
        __nv_bfloat16 hh2, ll2;
        split1(nd, hh2, ll2);
        g_Ch[(size_t)i * 768 + h] = hh2; g_Cl[(size_t)i * 768 + h] = ll2;
        split1(m, hh2, ll2);
        g_Ch[(size_t)i * 768 + 256 + h] = hh2; g_Cl[(size_t)i * 768 + 256 + h] = ll2;
    } else {
        // ---------------- edge ----------------
        int gid = (bid - 2 * NN) * 256 + t;
        int e = gid >> 6;
        int c = (gid & 63) << 2;
        int r = ei[e], cl = ei[NE + e];
        float4 p = *(const float4*)&g_T[(size_t)r * 768 + 256 + c];
        float4 q = *(const float4*)&g_T[(size_t)cl * 768 + 512 + c];
        float4 o;
        o.x = p.x + q.x; o.y = p.y + q.y; o.z = p.z + q.z; o.w = p.w + q.w;
        *(float4*)&out_edge[(size_t)e * 256 + c] = o;
    }
}

// ======================= launch =======================
extern "C" void kernel_launch(void* const* d_in, const int* in_sizes, int n_in,
                              void* d_out, int out_size) {
    const float* x   = (const float*)d_in[0];
    const int*   ei  = (const int*)  d_in[1];
    const float* Wn  = (const float*)d_in[2];
    const float* bn  = (const float*)d_in[3];
    const float* We  = (const float*)d_in[4];
    const float* be  = (const float*)d_in[5];
    const float* Ws1 = (const float*)d_in[6];
    const float* bs1 = (const float*)d_in[7];
    const float* Ws2 = (const float*)d_in[8];
    const float* bs2 = (const float*)d_in[9];
    const float* Wh1 = (const float*)d_in[10];
    const float* bh1 = (const float*)d_in[11];
    const float* Wh2 = (const float*)d_in[12];
    const float* bh2 = (const float*)d_in[13];

    float* out      = (float*)d_out;
    float* out_node = out;
    float* out_edge = out_node + (size_t)NN * HD;
    float* out_sub  = out_edge + (size_t)NE * HD;
    float* out_nbh  = out_sub  + (size_t)NN * HD;

    float* T;
    cudaGetSymbolAddress((void**)&T, g_T);
    __nv_bfloat16 *xh, *xl, *Chh, *Cll, *shh, *shl, *nhh, *nhl;
    __nv_bfloat16 *btc_h, *btc_l, *bs1h, *bs1l, *bs2h, *bs2l, *bh1h, *bh1l, *bh2h, *bh2l;
    __nv_bfloat16 *eB1, *eB2, *eB3, *eB4, *eB5;
    cudaGetSymbolAddress((void**)&xh, g_xh);   cudaGetSymbolAddress((void**)&xl, g_xl);
    cudaGetSymbolAddress((void**)&Chh, g_Ch);  cudaGetSymbolAddress((void**)&Cll, g_Cl);
    cudaGetSymbolAddress((void**)&shh, g_shh); cudaGetSymbolAddress((void**)&shl, g_shl);
    cudaGetSymbolAddress((void**)&nhh, g_nhh); cudaGetSymbolAddress((void**)&nhl, g_nhl);
    cudaGetSymbolAddress((void**)&btc_h, g_btc_h); cudaGetSymbolAddress((void**)&btc_l, g_btc_l);
    cudaGetSymbolAddress((void**)&bs1h, g_bs1_h);  cudaGetSymbolAddress((void**)&bs1l, g_bs1_l);
    cudaGetSymbolAddress((void**)&bs2h, g_bs2_h);  cudaGetSymbolAddress((void**)&bs2l, g_bs2_l);
    cudaGetSymbolAddress((void**)&bh1h, g_bh1_h);  cudaGetSymbolAddress((void**)&bh1l, g_bh1_l);
    cudaGetSymbolAddress((void**)&bh2h, g_bh2_h);  cudaGetSymbolAddress((void**)&bh2l, g_bh2_l);
    cudaGetSymbolAddress((void**)&eB1, g_extB1);
    cudaGetSymbolAddress((void**)&eB2, g_extB2);
    cudaGetSymbolAddress((void**)&eB3, g_extB3);
    cudaGetSymbolAddress((void**)&eB4, g_extB4);
    cudaGetSymbolAddress((void**)&eB5, g_extB5);

    // fused prep (+hist): 1,732,608 items
    prep_k<<<6768, 256>>>(x, ei, Wn, bn, We, be, Ws1, bs1, Ws2, bs2, Wh1, bh1, Wh2, bh2);

    // G1: T = x @ [Wn|We_a|We_b] + bcat   M=4096 K=128 N=768 (fp32 out)
    {
        GemmArgs a1 = { xh, xl, btc_h, btc_l, eB1, T, nullptr, nullptr,
                        FD, FD, 768, 0, FD, 0 };
        gemm_wmma1<<<dim3(6, 64), 256>>>(a1);
    }

    scan_k<<<1, 1024>>>();
    fillmisc_k<<<(2 * NE + NN * HD) / 256, 256>>>(ei);   // fill + bitmask + node->bf16

    // fused graph: mean2 (first) + mean1 + edge
    graph_k<<<2 * NN + (NE * 64) / 256, 256>>>(ei, out_node, out_edge);

    // batched {G2, G4}: both read C, write sh / nh (bf16 h/l, relu)
    {
        GemmArgs a2 = { Chh, Cll, bs1h, bs1l, eB2, nullptr, shh, shl,
                        768, 512, 0, 256, 512, 1 };
        GemmArgs a4 = { Chh, Cll, bh1h, bh1l, eB4, nullptr, nhh, nhl,
                        768, 768, 0, 256, 768, 1 };
        gemm_wmma2<<<dim3(2, 64, 2), 256>>>(a2, a4);
    }
    // batched {G3, G5}: sh@Ws2 -> out_sub, nh@Wh2 -> out_nbh (fp32)
    {
        GemmArgs a3 = { shh, shl, bs2h, bs2l, eB3, out_sub, nullptr, nullptr,
                        256, 256, 256, 0, 256, 0 };
        GemmArgs a5 = { nhh, nhl, bh2h, bh2l, eB5, out_nbh, nullptr, nullptr,
                        256, 256, 256, 0, 256, 0 };
        gemm_wmma2<<<dim3(2, 64, 2), 256>>>(a3, a5);
    }
}